// round 3
// baseline (speedup 1.0000x reference)
#include <cuda_runtime.h>
#include <cuda_bf16.h>
#include <cstddef>

// Problem constants
#define BB   16
#define WW   64
#define VV   64
#define DD   256
#define RR   64
#define NN   (WW*VV)          // 4096
#define PAD  68               // padded row stride for transposed tiles

// ---------------------------------------------------------------------------
// Scratch (static device globals; no runtime allocation)
// ---------------------------------------------------------------------------
__device__ float g_A  [BB*WW*DD];          // gathered head embeddings
__device__ float g_Bt [BB*VV*DD];          // gathered tail embeddings
__device__ float g_AW [BB*WW*DD];          // A @ fc_w[0:256]   + fc_b
__device__ float g_BW [BB*VV*DD];          // Bt @ fc_w[256:512]
__device__ float g_RW [RR*DD];             // rela @ fc_w[512:768]
__device__ float g_tv [(size_t)BB*NN*DD];  // tuple_vec (64 MB)
__device__ float g_att[BB*NN];             // att pre-softmax
__device__ float g_fuse[BB*DD];            // fused vector accumulators

__device__ __forceinline__ float tanh_fast(float x) {
    float y;
    asm("tanh.approx.f32 %0, %1;" : "=f"(y) : "f"(x));
    return y;
}

// ---------------------------------------------------------------------------
// Kernel P: gather embeddings + precompute AW / BW / RW (132 blocks x 256)
//   blocks 0..63  : AW rows (b,i) 16 at a time (also writes g_A)
//   blocks 64..127: BW rows (b,j) 16 at a time (also writes g_Bt)
//   blocks 128..131: RW rows (r)  16 at a time
// ---------------------------------------------------------------------------
__global__ __launch_bounds__(256) void kPre(
    const int* __restrict__ head, const int* __restrict__ tail,
    const float* __restrict__ emb, const float* __restrict__ rela,
    const float* __restrict__ fc_w, const float* __restrict__ fc_b)
{
    __shared__ float sX[16][DD];
    const int g = blockIdx.x, t = threadIdx.x;
    const int kind = (g < 64) ? 0 : (g < 128 ? 1 : 2);
    const int row0 = ((kind == 0) ? g : (kind == 1) ? (g - 64) : (g - 128)) * 16;

    #pragma unroll 4
    for (int rr = 0; rr < 16; ++rr) {
        const int row = row0 + rr;
        float v;
        if (kind == 0)      v = emb[(size_t)head[row] * DD + t];
        else if (kind == 1) v = emb[(size_t)tail[row] * DD + t];
        else                v = rela[row * DD + t];
        sX[rr][t] = v;
        if (kind == 0)      g_A [row * DD + t] = v;
        else if (kind == 1) g_Bt[row * DD + t] = v;
    }
    __syncthreads();

    const float* Wp = fc_w + (size_t)kind * DD * DD;
    float acc[16];
    #pragma unroll
    for (int r = 0; r < 16; ++r) acc[r] = (kind == 0) ? fc_b[t] : 0.0f;

    #pragma unroll 4
    for (int k = 0; k < DD; ++k) {
        const float wv = Wp[k * DD + t];
        #pragma unroll
        for (int r = 0; r < 16; ++r) acc[r] = fmaf(sX[r][k], wv, acc[r]);
    }

    float* dst = (kind == 0) ? g_AW : (kind == 1) ? g_BW : g_RW;
    #pragma unroll
    for (int r = 0; r < 16; ++r) dst[(row0 + r) * DD + t] = acc[r];
}

// ---------------------------------------------------------------------------
// Kernel M: main fused kernel. Block = (b, i). 1024 blocks x 256 threads.
//   GEMM1: S[j,r]  = sum_d (A_i[d]*Bt[j,d]) * rela[r,d]   (64x64, K=256)
//   mask + row softmax -> P (norm_scores out)
//   GEMM2: PV[j,d] = P @ RW, tv = tanh(AW_i + BW_j + PV)  (64x256, K=64)
//   GEMM3: Hid = tv @ att_w1, att = tanh(Hid+b1) @ att_w2 + b2
// ---------------------------------------------------------------------------
#define SMEM_M_FLOATS (2*DD*PAD + 64*PAD + 4*DD)
#define SMEM_M_BYTES  (SMEM_M_FLOATS * 4)

__global__ __launch_bounds__(256, 1) void kMain(
    const float* __restrict__ rela,   const float* __restrict__ att_w1,
    const float* __restrict__ att_b1, const float* __restrict__ att_w2,
    const float* __restrict__ att_b2, float* __restrict__ out_ns)
{
    const int t  = threadIdx.x;
    const int b  = blockIdx.x >> 6;
    const int i  = blockIdx.x & 63;
    const int tx = t & 15, ty = t >> 4;
    const int j0 = ty * 4, r0 = tx * 4;

    extern __shared__ float sm[];
    float* sBt = sm;                    // [256][PAD]  H^T = (A*Bt)^T, later tv^T
    float* sW  = sm + DD * PAD;         // [256][PAD] rela^T; later RW / att_w1 chunk [64][256]
    float* sP  = sW + DD * PAD;         // [64][PAD]  scores -> probs
    float* sA  = sP + 64 * PAD;         // 256
    float* sAW = sA + DD;               // 256
    float* sb1 = sAW + DD;              // 256
    float* sw2 = sb1 + DD;              // 256

    const int rowA = b * WW + i;
    sA [t] = g_A [rowA * DD + t];
    sAW[t] = g_AW[rowA * DD + t];
    sb1[t] = att_b1[t];
    sw2[t] = att_w2[t];
    __syncthreads();

    // Load Bt (x A, fused hadamard) and rela, both transposed k(d)-major.
    #pragma unroll 4
    for (int j = 0; j < 64; ++j) {
        sBt[t * PAD + j] = g_Bt[(b * VV + j) * DD + t] * sA[t];
        sW [t * PAD + j] = rela[j * DD + t];
    }
    __syncthreads();

    // ---- GEMM1: S = H @ rela^T (64x64) ----
    float c1[4][4];
    #pragma unroll
    for (int u = 0; u < 4; ++u)
        #pragma unroll
        for (int v = 0; v < 4; ++v) c1[u][v] = 0.0f;

    #pragma unroll 2
    for (int d = 0; d < DD; ++d) {
        const float4 h4 = *(const float4*)&sBt[d * PAD + j0];
        const float4 r4 = *(const float4*)&sW [d * PAD + r0];
        const float hj[4] = {h4.x, h4.y, h4.z, h4.w};
        const float rv[4] = {r4.x, r4.y, r4.z, r4.w};
        #pragma unroll
        for (int u = 0; u < 4; ++u)
            #pragma unroll
            for (int v = 0; v < 4; ++v)
                c1[u][v] = fmaf(hj[u], rv[v], c1[u][v]);
    }
    #pragma unroll
    for (int u = 0; u < 4; ++u)
        *(float4*)&sP[(j0 + u) * PAD + r0] =
            make_float4(c1[u][0], c1[u][1], c1[u][2], c1[u][3]);
    __syncthreads();

    // ---- mask + row softmax over R (4 threads per row, same warp) ----
    {
        const int j = t >> 2, q = t & 3;
        const float nul = sP[j * PAD + 63];
        float v[16];
        float mx = -1e30f;
        #pragma unroll
        for (int m = 0; m < 16; ++m) {
            float s = sP[j * PAD + q * 16 + m];
            s = (s <= nul) ? -1e10f : s;
            v[m] = s;
            mx = fmaxf(mx, s);
        }
        mx = fmaxf(mx, __shfl_xor_sync(0xffffffffu, mx, 1));
        mx = fmaxf(mx, __shfl_xor_sync(0xffffffffu, mx, 2));
        float se = 0.0f;
        #pragma unroll
        for (int m = 0; m < 16; ++m) { v[m] = expf(v[m] - mx); se += v[m]; }
        se += __shfl_xor_sync(0xffffffffu, se, 1);
        se += __shfl_xor_sync(0xffffffffu, se, 2);
        const float inv = 1.0f / se;
        #pragma unroll
        for (int m = 0; m < 16; ++m) sP[j * PAD + q * 16 + m] = v[m] * inv;
    }
    __syncthreads();

    // write norm_scores + load RW into sW
    const size_t ns_base = ((size_t)(b * NN + i * VV)) * RR;
    #pragma unroll
    for (int it = 0; it < 16; ++it) {
        const int l = it * 256 + t;
        const int j = l >> 6, r = l & 63;
        out_ns[ns_base + (size_t)j * RR + r] = sP[j * PAD + r];
    }
    #pragma unroll 4
    for (int it = 0; it < 64; ++it)
        sW[it * DD + t] = g_RW[it * DD + t];
    __syncthreads();

    // ---- GEMM2: PV = P @ RW (64x256, K=64); tv epilogue ----
    float a2[4][16];
    #pragma unroll
    for (int u = 0; u < 4; ++u)
        #pragma unroll
        for (int e = 0; e < 16; ++e) a2[u][e] = 0.0f;

    #pragma unroll 2
    for (int r = 0; r < 64; ++r) {
        float pj[4];
        #pragma unroll
        for (int u = 0; u < 4; ++u) pj[u] = sP[(j0 + u) * PAD + r];
        #pragma unroll
        for (int cc = 0; cc < 4; ++cc) {
            const float4 w4 = *(const float4*)&sW[r * DD + cc * 64 + tx * 4];
            const float wv[4] = {w4.x, w4.y, w4.z, w4.w};
            #pragma unroll
            for (int u = 0; u < 4; ++u)
                #pragma unroll
                for (int v = 0; v < 4; ++v)
                    a2[u][cc * 4 + v] = fmaf(pj[u], wv[v], a2[u][cc * 4 + v]);
        }
    }

    const size_t tvBase = ((size_t)(b * NN + i * VV)) * DD;
    #pragma unroll
    for (int u = 0; u < 4; ++u) {
        const int j = j0 + u;
        #pragma unroll
        for (int cc = 0; cc < 4; ++cc) {
            const int d0 = cc * 64 + tx * 4;
            const float4 bw = *(const float4*)&g_BW[(size_t)(b * VV + j) * DD + d0];
            float4 tv;
            tv.x = tanh_fast(a2[u][cc * 4 + 0] + sAW[d0 + 0] + bw.x);
            tv.y = tanh_fast(a2[u][cc * 4 + 1] + sAW[d0 + 1] + bw.y);
            tv.z = tanh_fast(a2[u][cc * 4 + 2] + sAW[d0 + 2] + bw.z);
            tv.w = tanh_fast(a2[u][cc * 4 + 3] + sAW[d0 + 3] + bw.w);
            *(float4*)&g_tv[tvBase + (size_t)j * DD + d0] = tv;
            sBt[(d0 + 0) * PAD + j] = tv.x;   // tv^T for GEMM3
            sBt[(d0 + 1) * PAD + j] = tv.y;
            sBt[(d0 + 2) * PAD + j] = tv.z;
            sBt[(d0 + 3) * PAD + j] = tv.w;
        }
    }
    __syncthreads();

    // ---- GEMM3: Hid = tv @ att_w1 (64x256, K=256), streamed in 4 k-chunks ----
    float a3[4][16];
    #pragma unroll
    for (int u = 0; u < 4; ++u)
        #pragma unroll
        for (int e = 0; e < 16; ++e) a3[u][e] = 0.0f;

    for (int kk = 0; kk < 4; ++kk) {
        const float4* wsrc = (const float4*)(att_w1 + (size_t)kk * 64 * DD);
        float4* wdst = (float4*)sW;
        #pragma unroll
        for (int it = 0; it < 16; ++it)
            wdst[it * 256 + t] = wsrc[it * 256 + t];
        __syncthreads();

        #pragma unroll 2
        for (int k = 0; k < 64; ++k) {
            const float4 t4 = *(const float4*)&sBt[(kk * 64 + k) * PAD + j0];
            const float tj[4] = {t4.x, t4.y, t4.z, t4.w};
            #pragma unroll
            for (int cc = 0; cc < 4; ++cc) {
                const float4 w4 = *(const float4*)&sW[k * DD + cc * 64 + tx * 4];
                const float wv[4] = {w4.x, w4.y, w4.z, w4.w};
                #pragma unroll
                for (int u = 0; u < 4; ++u)
                    #pragma unroll
                    for (int v = 0; v < 4; ++v)
                        a3[u][cc * 4 + v] = fmaf(tj[u], wv[v], a3[u][cc * 4 + v]);
            }
        }
        __syncthreads();
    }

    // ---- epilogue: att[j] = tanh(Hid + b1) . att_w2 + b2 ----
    float patt[4] = {0.0f, 0.0f, 0.0f, 0.0f};
    #pragma unroll
    for (int u = 0; u < 4; ++u)
        #pragma unroll
        for (int cc = 0; cc < 4; ++cc)
            #pragma unroll
            for (int v = 0; v < 4; ++v) {
                const int d = cc * 64 + tx * 4 + v;
                const float h = tanh_fast(a3[u][cc * 4 + v] + sb1[d]);
                patt[u] = fmaf(h, sw2[d], patt[u]);
            }
    #pragma unroll
    for (int u = 0; u < 4; ++u) {
        patt[u] += __shfl_xor_sync(0xffffffffu, patt[u], 1);
        patt[u] += __shfl_xor_sync(0xffffffffu, patt[u], 2);
        patt[u] += __shfl_xor_sync(0xffffffffu, patt[u], 4);
        patt[u] += __shfl_xor_sync(0xffffffffu, patt[u], 8);
    }
    if (tx == 0) {
        const float b2v = att_b2[0];
        #pragma unroll
        for (int u = 0; u < 4; ++u)
            g_att[b * NN + i * VV + j0 + u] = patt[u] + b2v;
    }
}

// ---------------------------------------------------------------------------
// Kernel F1: softmax over N of att per batch; writes att_norms; zeroes g_fuse
// ---------------------------------------------------------------------------
__global__ __launch_bounds__(256) void kAtt(float* __restrict__ out_attn)
{
    const int b = blockIdx.x, t = threadIdx.x;
    __shared__ float red[8];
    float vals[16];
    float mx = -1e30f;
    #pragma unroll
    for (int it = 0; it < 16; ++it) {
        vals[it] = g_att[b * NN + it * 256 + t];
        mx = fmaxf(mx, vals[it]);
    }
    #pragma unroll
    for (int o = 16; o; o >>= 1) mx = fmaxf(mx, __shfl_xor_sync(0xffffffffu, mx, o));
    if ((t & 31) == 0) red[t >> 5] = mx;
    __syncthreads();
    float bm = red[0];
    #pragma unroll
    for (int w = 1; w < 8; ++w) bm = fmaxf(bm, red[w]);
    __syncthreads();

    float s = 0.0f;
    #pragma unroll
    for (int it = 0; it < 16; ++it) { vals[it] = expf(vals[it] - bm); s += vals[it]; }
    #pragma unroll
    for (int o = 16; o; o >>= 1) s += __shfl_xor_sync(0xffffffffu, s, o);
    if ((t & 31) == 0) red[t >> 5] = s;
    __syncthreads();
    float bs = 0.0f;
    #pragma unroll
    for (int w = 0; w < 8; ++w) bs += red[w];
    const float inv = 1.0f / bs;
    #pragma unroll
    for (int it = 0; it < 16; ++it)
        out_attn[b * NN + it * 256 + t] = vals[it] * inv;
    g_fuse[b * DD + t] = 0.0f;
}

// ---------------------------------------------------------------------------
// Kernel F2: fuse = sum_n att_norms[n] * tv[n,:]  (128 blocks: b x 8 chunks)
// ---------------------------------------------------------------------------
__global__ __launch_bounds__(256) void kFuse(const float* __restrict__ attn)
{
    const int b = blockIdx.x >> 3, ch = blockIdx.x & 7, t = threadIdx.x;
    __shared__ float sa[512];
    const int n0 = ch * 512;
    sa[t]       = attn[b * NN + n0 + t];
    sa[t + 256] = attn[b * NN + n0 + 256 + t];
    __syncthreads();

    const float* tvp = g_tv + ((size_t)(b * NN + n0)) * DD + t;
    float a0 = 0, a1 = 0, a2 = 0, a3 = 0;
    #pragma unroll 2
    for (int n = 0; n < 512; n += 4) {
        a0 = fmaf(sa[n + 0], tvp[(size_t)(n + 0) * DD], a0);
        a1 = fmaf(sa[n + 1], tvp[(size_t)(n + 1) * DD], a1);
        a2 = fmaf(sa[n + 2], tvp[(size_t)(n + 2) * DD], a2);
        a3 = fmaf(sa[n + 3], tvp[(size_t)(n + 3) * DD], a3);
    }
    atomicAdd(&g_fuse[b * DD + t], (a0 + a1) + (a2 + a3));
}

// ---------------------------------------------------------------------------
// Kernel F3: logits[b] = fuse . out_w + out_b
// ---------------------------------------------------------------------------
__global__ __launch_bounds__(256) void kLogits(
    float* __restrict__ out, const float* __restrict__ ow, const float* __restrict__ ob)
{
    const int b = blockIdx.x, t = threadIdx.x;
    __shared__ float red[8];
    float v = g_fuse[b * DD + t] * ow[t];
    #pragma unroll
    for (int o = 16; o; o >>= 1) v += __shfl_xor_sync(0xffffffffu, v, o);
    if ((t & 31) == 0) red[t >> 5] = v;
    __syncthreads();
    if (t == 0) {
        float s = 0.0f;
        #pragma unroll
        for (int w = 0; w < 8; ++w) s += red[w];
        out[b] = s + ob[0];
    }
}

// ---------------------------------------------------------------------------
// Launch
// ---------------------------------------------------------------------------
extern "C" void kernel_launch(void* const* d_in, const int* in_sizes, int n_in,
                              void* d_out, int out_size)
{
    const int*   head = (const int*)d_in[0];
    const int*   tail = (const int*)d_in[1];
    const float* emb  = (const float*)d_in[2];
    const float* rela = (const float*)d_in[3];
    const float* fc_w = (const float*)d_in[4];
    const float* fc_b = (const float*)d_in[5];
    const float* aw1  = (const float*)d_in[6];
    const float* ab1  = (const float*)d_in[7];
    const float* aw2  = (const float*)d_in[8];
    const float* ab2  = (const float*)d_in[9];
    const float* ow   = (const float*)d_in[10];
    const float* ob   = (const float*)d_in[11];

    float* out        = (float*)d_out;
    float* out_logits = out;
    float* out_attn   = out + BB;
    float* out_ns     = out + BB + BB * NN;

    cudaFuncSetAttribute(kMain, cudaFuncAttributeMaxDynamicSharedMemorySize, SMEM_M_BYTES);

    kPre   <<<132,  256>>>(head, tail, emb, rela, fc_w, fc_b);
    kMain  <<<BB*WW, 256, SMEM_M_BYTES>>>(rela, aw1, ab1, aw2, ab2, out_ns);
    kAtt   <<<BB,   256>>>(out_attn);
    kFuse  <<<BB*8, 256>>>(out_attn);
    kLogits<<<BB,   256>>>(out_logits, ow, ob);
}

// round 4
// speedup vs baseline: 1.1729x; 1.1729x over previous
#include <cuda_runtime.h>
#include <cuda_bf16.h>
#include <cstddef>

// Problem constants
#define BB   16
#define WW   64
#define VV   64
#define DD   256
#define RR   64
#define NN   (WW*VV)          // 4096
#define PAD  68               // padded row stride for d-major transposed tiles
#define PAD2 260              // padded row stride for tv row-major tile

typedef unsigned long long ull;

// ---------------------------------------------------------------------------
// Scratch (static device globals; no runtime allocation)
// ---------------------------------------------------------------------------
__device__ float g_A   [BB*WW*DD];          // gathered head embeddings
__device__ float g_BtT [BB*DD*VV];          // tail embeddings, transposed per b: [b][d][j]
__device__ float g_relaT[DD*RR];            // rela transposed: [d][r]
__device__ float g_AW  [BB*WW*DD];          // A @ fc_w[0:256]   + fc_b
__device__ float g_BW  [BB*VV*DD];          // Bt @ fc_w[256:512]
__device__ float g_RW  [RR*DD];             // rela @ fc_w[512:768]
__device__ float g_tv  [(size_t)BB*NN*DD];  // tuple_vec (64 MB)
__device__ float g_att [BB*NN];             // att pre-softmax
__device__ float g_fuse[BB*DD];             // fused vector accumulators

__device__ __forceinline__ float tanh_fast(float x) {
    float y;
    asm("tanh.approx.f32 %0, %1;" : "=f"(y) : "f"(x));
    return y;
}
// packed fp32x2 helpers (Blackwell FFMA2 path)
__device__ __forceinline__ ull fma2(ull a, ull b, ull c) {
    ull d;
    asm("fma.rn.f32x2 %0, %1, %2, %3;" : "=l"(d) : "l"(a), "l"(b), "l"(c));
    return d;
}
__device__ __forceinline__ ull pack2(float x) {
    ull r;
    asm("mov.b64 %0, {%1, %1};" : "=l"(r) : "f"(x));
    return r;
}
__device__ __forceinline__ float2 unpack2(ull v) {
    float2 f;
    asm("mov.b64 {%0, %1}, %2;" : "=f"(f.x), "=f"(f.y) : "l"(v));
    return f;
}

// ---------------------------------------------------------------------------
// Kernel P: gather embeddings + precompute AW / BW / RW + transposed copies
//   blocks 0..63  : AW rows (b,i) 16 at a time (also writes g_A)
//   blocks 64..127: BW rows (b,j) 16 at a time (also writes g_BtT transposed)
//   blocks 128..131: RW rows (r)  16 at a time (also writes g_relaT)
// ---------------------------------------------------------------------------
__global__ __launch_bounds__(256) void kPre(
    const int* __restrict__ head, const int* __restrict__ tail,
    const float* __restrict__ emb, const float* __restrict__ rela,
    const float* __restrict__ fc_w, const float* __restrict__ fc_b)
{
    __shared__ float sX[16][257];
    const int g = blockIdx.x, t = threadIdx.x;
    const int kind = (g < 64) ? 0 : (g < 128 ? 1 : 2);
    const int row0 = ((kind == 0) ? g : (kind == 1) ? (g - 64) : (g - 128)) * 16;

    #pragma unroll 4
    for (int rr = 0; rr < 16; ++rr) {
        const int row = row0 + rr;
        float v;
        if (kind == 0)      v = emb[(size_t)head[row] * DD + t];
        else if (kind == 1) v = emb[(size_t)tail[row] * DD + t];
        else                v = rela[row * DD + t];
        sX[rr][t] = v;
        if (kind == 0)      g_A[row * DD + t] = v;
    }
    __syncthreads();

    const float* Wp = fc_w + (size_t)kind * DD * DD;
    float acc[16];
    #pragma unroll
    for (int r = 0; r < 16; ++r) acc[r] = (kind == 0) ? fc_b[t] : 0.0f;

    #pragma unroll 4
    for (int k = 0; k < DD; ++k) {
        const float wv = Wp[k * DD + t];
        #pragma unroll
        for (int r = 0; r < 16; ++r) acc[r] = fmaf(sX[r][k], wv, acc[r]);
    }

    float* dst = (kind == 0) ? g_AW : (kind == 1) ? g_BW : g_RW;
    #pragma unroll
    for (int r = 0; r < 16; ++r) dst[(row0 + r) * DD + t] = acc[r];

    // transposed copies for kMain's d-major tiles
    if (kind != 0) {
        float* dstT = (kind == 1)
            ? (g_BtT + (size_t)(row0 >> 6) * DD * VV + (row0 & 63))
            : (g_relaT + row0);
        #pragma unroll
        for (int it = 0; it < 4; ++it) {
            const int f = it * 256 + t;     // 1024 float4s
            const int d = f >> 2;
            const int q = f & 3;
            float4 v;
            v.x = sX[q * 4 + 0][d];
            v.y = sX[q * 4 + 1][d];
            v.z = sX[q * 4 + 2][d];
            v.w = sX[q * 4 + 3][d];
            *(float4*)&dstT[d * 64 + q * 4] = v;
        }
    }
}

// ---------------------------------------------------------------------------
// Kernel M: main fused kernel. Block = (b, i). 1024 blocks x 256 threads.
//   GEMM1: S[j,r]  = sum_d (A_i[d]*Bt[j,d]) * rela[r,d]   (64x64, K=256)
//   mask + row softmax -> P (norm_scores out)
//   GEMM2: PV[j,d] = P @ RW, tv = tanh(AW_i + BW_j + PV)  (64x256, K=64)
//   GEMM3: Hid = tv @ att_w1, att = tanh(Hid+b1) @ att_w2 + b2
// All GEMMs use packed fp32x2 FMA.
// ---------------------------------------------------------------------------
#define SMEM_M_FLOATS (2*DD*PAD + 64*PAD + 4*DD)
#define SMEM_M_BYTES  (SMEM_M_FLOATS * 4)

__global__ __launch_bounds__(256, 1) void kMain(
    const float* __restrict__ att_w1, const float* __restrict__ att_b1,
    const float* __restrict__ att_w2, const float* __restrict__ att_b2,
    float* __restrict__ out_ns)
{
    const int t  = threadIdx.x;
    const int b  = blockIdx.x >> 6;
    const int i  = blockIdx.x & 63;
    const int tx = t & 15, ty = t >> 4;
    const int j0 = ty * 4, r0 = tx * 4;

    extern __shared__ float sm[];
    float* sBt = sm;                    // region1: [256][PAD] H^T; later sTv [64][PAD2]
    float* sW  = sm + DD * PAD;         // region2: [256][PAD] rela^T; later RW / w1 chunk [64][256]
    float* sP  = sW + DD * PAD;         // [64][PAD]  scores -> probs
    float* sA  = sP + 64 * PAD;         // 256
    float* sAW = sA + DD;               // 256
    float* sb1 = sAW + DD;              // 256
    float* sw2 = sb1 + DD;              // 256
    float* sTv = sBt;                   // alias after GEMM1

    const int rowA = b * WW + i;
    sA [t] = g_A [rowA * DD + t];
    sAW[t] = g_AW[rowA * DD + t];
    sb1[t] = att_b1[t];
    sw2[t] = att_w2[t];
    __syncthreads();

    // Fill H^T = (A_i * Bt)^T and rela^T tiles (d-major), coalesced gmem reads.
    #pragma unroll 4
    for (int it = 0; it < 16; ++it) {
        const int f = it * 256 + t;       // 4096 float4s
        const int d = f >> 4;
        const int c = (f & 15) * 4;
        float4 bv = *(const float4*)&g_BtT[(size_t)b * DD * VV + d * 64 + c];
        const float sa = sA[d];
        bv.x *= sa; bv.y *= sa; bv.z *= sa; bv.w *= sa;
        *(float4*)&sBt[d * PAD + c] = bv;
        *(float4*)&sW [d * PAD + c] = *(const float4*)&g_relaT[d * 64 + c];
    }
    __syncthreads();

    // ---- GEMM1: S = H @ rela^T (64x64, K=256), packed fp32x2 ----
    ull c1[4][2];
    #pragma unroll
    for (int u = 0; u < 4; ++u) { c1[u][0] = 0ull; c1[u][1] = 0ull; }

    #pragma unroll 4
    for (int d = 0; d < DD; ++d) {
        const float4 h4 = *(const float4*)&sBt[d * PAD + j0];
        const ulonglong2 r2 = *(const ulonglong2*)&sW[d * PAD + r0];
        const ull hp[4] = {pack2(h4.x), pack2(h4.y), pack2(h4.z), pack2(h4.w)};
        #pragma unroll
        for (int u = 0; u < 4; ++u) {
            c1[u][0] = fma2(hp[u], r2.x, c1[u][0]);
            c1[u][1] = fma2(hp[u], r2.y, c1[u][1]);
        }
    }
    #pragma unroll
    for (int u = 0; u < 4; ++u) {
        const float2 lo = unpack2(c1[u][0]);
        const float2 hi = unpack2(c1[u][1]);
        *(float4*)&sP[(j0 + u) * PAD + r0] = make_float4(lo.x, lo.y, hi.x, hi.y);
    }
    __syncthreads();

    // ---- mask + row softmax over R (4 threads per row, same warp) ----
    {
        const int j = t >> 2, q = t & 3;
        const float nul = sP[j * PAD + 63];
        float v[16];
        float mx = -1e30f;
        #pragma unroll
        for (int m = 0; m < 16; ++m) {
            float s = sP[j * PAD + q * 16 + m];
            s = (s <= nul) ? -1e10f : s;
            v[m] = s;
            mx = fmaxf(mx, s);
        }
        mx = fmaxf(mx, __shfl_xor_sync(0xffffffffu, mx, 1));
        mx = fmaxf(mx, __shfl_xor_sync(0xffffffffu, mx, 2));
        float se = 0.0f;
        #pragma unroll
        for (int m = 0; m < 16; ++m) { v[m] = expf(v[m] - mx); se += v[m]; }
        se += __shfl_xor_sync(0xffffffffu, se, 1);
        se += __shfl_xor_sync(0xffffffffu, se, 2);
        const float inv = 1.0f / se;
        #pragma unroll
        for (int m = 0; m < 16; ++m) sP[j * PAD + q * 16 + m] = v[m] * inv;
    }
    __syncthreads();

    // write norm_scores + load RW into sW (row-major [64][256])
    const size_t ns_base = ((size_t)(b * NN + i * VV)) * RR;
    #pragma unroll
    for (int it = 0; it < 16; ++it) {
        const int l = it * 256 + t;
        const int j = l >> 6, r = l & 63;
        out_ns[ns_base + (size_t)j * RR + r] = sP[j * PAD + r];
    }
    #pragma unroll 4
    for (int it = 0; it < 16; ++it)
        ((float4*)sW)[it * 256 + t] = ((const float4*)g_RW)[it * 256 + t];
    __syncthreads();

    // ---- GEMM2: PV = P @ RW (64x256, K=64), packed; tv epilogue ----
    ull a2[4][8];
    #pragma unroll
    for (int u = 0; u < 4; ++u)
        #pragma unroll
        for (int e = 0; e < 8; ++e) a2[u][e] = 0ull;

    #pragma unroll 2
    for (int r = 0; r < 64; ++r) {
        ull pp[4];
        #pragma unroll
        for (int u = 0; u < 4; ++u) pp[u] = pack2(sP[(j0 + u) * PAD + r]);
        #pragma unroll
        for (int cc = 0; cc < 4; ++cc) {
            const ulonglong2 w2 = *(const ulonglong2*)&sW[r * DD + cc * 64 + tx * 4];
            #pragma unroll
            for (int u = 0; u < 4; ++u) {
                a2[u][cc * 2 + 0] = fma2(pp[u], w2.x, a2[u][cc * 2 + 0]);
                a2[u][cc * 2 + 1] = fma2(pp[u], w2.y, a2[u][cc * 2 + 1]);
            }
        }
    }

    const size_t tvBase = ((size_t)(b * NN + i * VV)) * DD;
    #pragma unroll
    for (int u = 0; u < 4; ++u) {
        const int j = j0 + u;
        #pragma unroll
        for (int cc = 0; cc < 4; ++cc) {
            const int d0 = cc * 64 + tx * 4;
            const float4 bw = *(const float4*)&g_BW[(size_t)(b * VV + j) * DD + d0];
            const float2 p0 = unpack2(a2[u][cc * 2 + 0]);
            const float2 p1 = unpack2(a2[u][cc * 2 + 1]);
            float4 tv;
            tv.x = tanh_fast(p0.x + sAW[d0 + 0] + bw.x);
            tv.y = tanh_fast(p0.y + sAW[d0 + 1] + bw.y);
            tv.z = tanh_fast(p1.x + sAW[d0 + 2] + bw.z);
            tv.w = tanh_fast(p1.y + sAW[d0 + 3] + bw.w);
            *(float4*)&g_tv[tvBase + (size_t)j * DD + d0] = tv;
            *(float4*)&sTv[j * PAD2 + d0] = tv;       // row-major tv for GEMM3
        }
    }
    __syncthreads();

    // ---- GEMM3: Hid = tv @ att_w1 (64x256, K=256), packed, 4 k-chunks ----
    ull a3[4][8];
    #pragma unroll
    for (int u = 0; u < 4; ++u)
        #pragma unroll
        for (int e = 0; e < 8; ++e) a3[u][e] = 0ull;

    for (int kk = 0; kk < 4; ++kk) {
        const float4* wsrc = (const float4*)(att_w1 + (size_t)kk * 64 * DD);
        #pragma unroll 4
        for (int it = 0; it < 16; ++it)
            ((float4*)sW)[it * 256 + t] = wsrc[it * 256 + t];
        __syncthreads();

        #pragma unroll 2
        for (int k = 0; k < 64; ++k) {
            const int ka = kk * 64 + k;
            ull tp[4];
            #pragma unroll
            for (int u = 0; u < 4; ++u) tp[u] = pack2(sTv[(j0 + u) * PAD2 + ka]);
            #pragma unroll
            for (int cc = 0; cc < 4; ++cc) {
                const ulonglong2 w2 = *(const ulonglong2*)&sW[k * DD + cc * 64 + tx * 4];
                #pragma unroll
                for (int u = 0; u < 4; ++u) {
                    a3[u][cc * 2 + 0] = fma2(tp[u], w2.x, a3[u][cc * 2 + 0]);
                    a3[u][cc * 2 + 1] = fma2(tp[u], w2.y, a3[u][cc * 2 + 1]);
                }
            }
        }
        __syncthreads();
    }

    // ---- epilogue: att[j] = tanh(Hid + b1) . att_w2 + b2 ----
    float patt[4] = {0.0f, 0.0f, 0.0f, 0.0f};
    #pragma unroll
    for (int u = 0; u < 4; ++u)
        #pragma unroll
        for (int cc = 0; cc < 4; ++cc) {
            const int d0 = cc * 64 + tx * 4;
            const float2 p0 = unpack2(a3[u][cc * 2 + 0]);
            const float2 p1 = unpack2(a3[u][cc * 2 + 1]);
            patt[u] = fmaf(tanh_fast(p0.x + sb1[d0 + 0]), sw2[d0 + 0], patt[u]);
            patt[u] = fmaf(tanh_fast(p0.y + sb1[d0 + 1]), sw2[d0 + 1], patt[u]);
            patt[u] = fmaf(tanh_fast(p1.x + sb1[d0 + 2]), sw2[d0 + 2], patt[u]);
            patt[u] = fmaf(tanh_fast(p1.y + sb1[d0 + 3]), sw2[d0 + 3], patt[u]);
        }
    #pragma unroll
    for (int u = 0; u < 4; ++u) {
        patt[u] += __shfl_xor_sync(0xffffffffu, patt[u], 1);
        patt[u] += __shfl_xor_sync(0xffffffffu, patt[u], 2);
        patt[u] += __shfl_xor_sync(0xffffffffu, patt[u], 4);
        patt[u] += __shfl_xor_sync(0xffffffffu, patt[u], 8);
    }
    if (tx == 0) {
        const float b2v = att_b2[0];
        #pragma unroll
        for (int u = 0; u < 4; ++u)
            g_att[b * NN + i * VV + j0 + u] = patt[u] + b2v;
    }
}

// ---------------------------------------------------------------------------
// Kernel F1: softmax over N of att per batch; writes att_norms; zeroes g_fuse
// ---------------------------------------------------------------------------
__global__ __launch_bounds__(256) void kAtt(float* __restrict__ out_attn)
{
    const int b = blockIdx.x, t = threadIdx.x;
    __shared__ float red[8];
    float vals[16];
    float mx = -1e30f;
    #pragma unroll
    for (int it = 0; it < 16; ++it) {
        vals[it] = g_att[b * NN + it * 256 + t];
        mx = fmaxf(mx, vals[it]);
    }
    #pragma unroll
    for (int o = 16; o; o >>= 1) mx = fmaxf(mx, __shfl_xor_sync(0xffffffffu, mx, o));
    if ((t & 31) == 0) red[t >> 5] = mx;
    __syncthreads();
    float bm = red[0];
    #pragma unroll
    for (int w = 1; w < 8; ++w) bm = fmaxf(bm, red[w]);
    __syncthreads();

    float s = 0.0f;
    #pragma unroll
    for (int it = 0; it < 16; ++it) { vals[it] = expf(vals[it] - bm); s += vals[it]; }
    #pragma unroll
    for (int o = 16; o; o >>= 1) s += __shfl_xor_sync(0xffffffffu, s, o);
    if ((t & 31) == 0) red[t >> 5] = s;
    __syncthreads();
    float bs = 0.0f;
    #pragma unroll
    for (int w = 0; w < 8; ++w) bs += red[w];
    const float inv = 1.0f / bs;
    #pragma unroll
    for (int it = 0; it < 16; ++it)
        out_attn[b * NN + it * 256 + t] = vals[it] * inv;
    g_fuse[b * DD + t] = 0.0f;
}

// ---------------------------------------------------------------------------
// Kernel F2: fuse = sum_n att_norms[n] * tv[n,:]  (512 blocks: b x 32 chunks)
// ---------------------------------------------------------------------------
__global__ __launch_bounds__(256) void kFuse(const float* __restrict__ attn)
{
    const int b = blockIdx.x >> 5, ch = blockIdx.x & 31, t = threadIdx.x;
    __shared__ float sa[128];
    const int n0 = ch * 128;
    if (t < 128) sa[t] = attn[b * NN + n0 + t];
    __syncthreads();

    const float* tvp = g_tv + ((size_t)(b * NN + n0)) * DD + t;
    float a0 = 0, a1 = 0, a2 = 0, a3 = 0, a4 = 0, a5 = 0, a6 = 0, a7 = 0;
    #pragma unroll
    for (int n = 0; n < 128; n += 8) {
        a0 = fmaf(sa[n + 0], tvp[(size_t)(n + 0) * DD], a0);
        a1 = fmaf(sa[n + 1], tvp[(size_t)(n + 1) * DD], a1);
        a2 = fmaf(sa[n + 2], tvp[(size_t)(n + 2) * DD], a2);
        a3 = fmaf(sa[n + 3], tvp[(size_t)(n + 3) * DD], a3);
        a4 = fmaf(sa[n + 4], tvp[(size_t)(n + 4) * DD], a4);
        a5 = fmaf(sa[n + 5], tvp[(size_t)(n + 5) * DD], a5);
        a6 = fmaf(sa[n + 6], tvp[(size_t)(n + 6) * DD], a6);
        a7 = fmaf(sa[n + 7], tvp[(size_t)(n + 7) * DD], a7);
    }
    atomicAdd(&g_fuse[b * DD + t], ((a0 + a1) + (a2 + a3)) + ((a4 + a5) + (a6 + a7)));
}

// ---------------------------------------------------------------------------
// Kernel F3: logits[b] = fuse . out_w + out_b
// ---------------------------------------------------------------------------
__global__ __launch_bounds__(256) void kLogits(
    float* __restrict__ out, const float* __restrict__ ow, const float* __restrict__ ob)
{
    const int b = blockIdx.x, t = threadIdx.x;
    __shared__ float red[8];
    float v = g_fuse[b * DD + t] * ow[t];
    #pragma unroll
    for (int o = 16; o; o >>= 1) v += __shfl_xor_sync(0xffffffffu, v, o);
    if ((t & 31) == 0) red[t >> 5] = v;
    __syncthreads();
    if (t == 0) {
        float s = 0.0f;
        #pragma unroll
        for (int w = 0; w < 8; ++w) s += red[w];
        out[b] = s + ob[0];
    }
}

// ---------------------------------------------------------------------------
// Launch
// ---------------------------------------------------------------------------
extern "C" void kernel_launch(void* const* d_in, const int* in_sizes, int n_in,
                              void* d_out, int out_size)
{
    const int*   head = (const int*)d_in[0];
    const int*   tail = (const int*)d_in[1];
    const float* emb  = (const float*)d_in[2];
    const float* rela = (const float*)d_in[3];
    const float* fc_w = (const float*)d_in[4];
    const float* fc_b = (const float*)d_in[5];
    const float* aw1  = (const float*)d_in[6];
    const float* ab1  = (const float*)d_in[7];
    const float* aw2  = (const float*)d_in[8];
    const float* ab2  = (const float*)d_in[9];
    const float* ow   = (const float*)d_in[10];
    const float* ob   = (const float*)d_in[11];

    float* out        = (float*)d_out;
    float* out_logits = out;
    float* out_attn   = out + BB;
    float* out_ns     = out + BB + BB * NN;

    cudaFuncSetAttribute(kMain, cudaFuncAttributeMaxDynamicSharedMemorySize, SMEM_M_BYTES);

    kPre   <<<132,   256>>>(head, tail, emb, rela, fc_w, fc_b);
    kMain  <<<BB*WW, 256, SMEM_M_BYTES>>>(aw1, ab1, aw2, ab2, out_ns);
    kAtt   <<<BB,    256>>>(out_attn);
    kFuse  <<<BB*32, 256>>>(out_attn);
    kLogits<<<BB,    256>>>(out_logits, ow, ob);
}

// round 6
// speedup vs baseline: 1.3272x; 1.1315x over previous
#include <cuda_runtime.h>
#include <cuda_bf16.h>
#include <cstdint>
#include <cstddef>

// Problem constants
#define BB   16
#define WW   64
#define VV   64
#define DD   256
#define RR   64
#define NN   (WW*VV)          // 4096
#define PAD  68               // padded stride for d-major tiles
#define PAD2 260              // padded stride for tv row-major tile

typedef unsigned long long ull;

// ---------------------------------------------------------------------------
// Scratch (static device globals)
// ---------------------------------------------------------------------------
__device__ float g_A   [BB*WW*DD];
__device__ float g_BtT [BB*DD*VV];
__device__ float g_relaT[DD*RR];
__device__ float g_AW  [BB*WW*DD];
__device__ float g_BW  [BB*VV*DD];
__device__ float g_RW  [RR*DD];
__device__ float g_tv  [(size_t)BB*NN*DD];   // tuple_vec (64 MB)
__device__ float g_att [BB*NN];
__device__ float g_fuse[BB*DD];

// ---------------------------------------------------------------------------
// helpers
// ---------------------------------------------------------------------------
__device__ __forceinline__ float tanh_fast(float x) {
    float y; asm("tanh.approx.f32 %0, %1;" : "=f"(y) : "f"(x)); return y;
}
__device__ __forceinline__ ull fma2(ull a, ull b, ull c) {
    ull d; asm("fma.rn.f32x2 %0, %1, %2, %3;" : "=l"(d) : "l"(a), "l"(b), "l"(c)); return d;
}
__device__ __forceinline__ ull pack2(float x) {
    ull r; asm("mov.b64 %0, {%1, %1};" : "=l"(r) : "f"(x)); return r;
}
__device__ __forceinline__ float2 unpack2(ull v) {
    float2 f; asm("mov.b64 {%0, %1}, %2;" : "=f"(f.x), "=f"(f.y) : "l"(v)); return f;
}
__device__ __forceinline__ uint32_t smem_u32(const void* p) {
    uint32_t a;
    asm("{ .reg .u64 tmp; cvta.to.shared.u64 tmp, %1; cvt.u32.u64 %0, tmp; }"
        : "=r"(a) : "l"(p));
    return a;
}
__device__ __forceinline__ void cp_async16(uint32_t daddr, const void* src) {
    asm volatile("cp.async.cg.shared.global [%0], [%1], 16;"
                 :: "r"(daddr), "l"(src) : "memory");
}
#define CP_COMMIT() asm volatile("cp.async.commit_group;" ::: "memory")
#define CP_WAIT0()  asm volatile("cp.async.wait_group 0;" ::: "memory")

// ---------------------------------------------------------------------------
// Kernel P: gather + AW/BW/RW precompute + transposed copies (132 blocks)
// ---------------------------------------------------------------------------
__global__ __launch_bounds__(256) void kPre(
    const int* __restrict__ head, const int* __restrict__ tail,
    const float* __restrict__ emb, const float* __restrict__ rela,
    const float* __restrict__ fc_w, const float* __restrict__ fc_b)
{
    __shared__ float sX[16][257];
    const int g = blockIdx.x, t = threadIdx.x;
    const int kind = (g < 64) ? 0 : (g < 128 ? 1 : 2);
    const int row0 = ((kind == 0) ? g : (kind == 1) ? (g - 64) : (g - 128)) * 16;

    #pragma unroll 4
    for (int rr = 0; rr < 16; ++rr) {
        const int row = row0 + rr;
        float v;
        if (kind == 0)      v = emb[(size_t)head[row] * DD + t];
        else if (kind == 1) v = emb[(size_t)tail[row] * DD + t];
        else                v = rela[row * DD + t];
        sX[rr][t] = v;
        if (kind == 0)      g_A[row * DD + t] = v;
    }
    __syncthreads();

    const float* Wp = fc_w + (size_t)kind * DD * DD;
    float acc[16];
    #pragma unroll
    for (int r = 0; r < 16; ++r) acc[r] = (kind == 0) ? fc_b[t] : 0.0f;

    #pragma unroll 4
    for (int k = 0; k < DD; ++k) {
        const float wv = Wp[k * DD + t];
        #pragma unroll
        for (int r = 0; r < 16; ++r) acc[r] = fmaf(sX[r][k], wv, acc[r]);
    }

    float* dst = (kind == 0) ? g_AW : (kind == 1) ? g_BW : g_RW;
    #pragma unroll
    for (int r = 0; r < 16; ++r) dst[(row0 + r) * DD + t] = acc[r];

    if (kind != 0) {
        float* dstT = (kind == 1)
            ? (g_BtT + (size_t)(row0 >> 6) * DD * VV + (row0 & 63))
            : (g_relaT + row0);
        #pragma unroll
        for (int it = 0; it < 4; ++it) {
            const int f = it * 256 + t;
            const int d = f >> 2;
            const int q = f & 3;
            float4 v;
            v.x = sX[q * 4 + 0][d];
            v.y = sX[q * 4 + 1][d];
            v.z = sX[q * 4 + 2][d];
            v.w = sX[q * 4 + 3][d];
            *(float4*)&dstT[d * 64 + q * 4] = v;
        }
    }
}

// ---------------------------------------------------------------------------
// Kernel M: fully fused. Block = (b, i). 1024 blocks x 256 threads.
// smem layout (floats):
//   s1 [0, 17408)      : H^T [256][PAD]  -> later sTv [64][PAD2]
//   s2 [17408, 50176)  : rela^T [256][PAD] -> later {RW | w1 buf lo} + {w1 buf hi}
//   sP [50176, 54528)  : scores/probs [64][PAD]
//   sA, sAW, sb1, sw2  : 4 x 256
// ---------------------------------------------------------------------------
#define SM_S1   0
#define SM_S2   17408
#define SM_SP   50176
#define SM_SA   54528
#define SM_SAW  54784
#define SM_SB1  55040
#define SM_SW2  55296
#define SMEM_M_FLOATS 55552
#define SMEM_M_BYTES  (SMEM_M_FLOATS * 4)

__global__ __launch_bounds__(256, 1) void kMain(
    const float* __restrict__ att_w1, const float* __restrict__ att_b1,
    const float* __restrict__ att_w2, const float* __restrict__ att_b2,
    float* __restrict__ out_ns)
{
    const int t  = threadIdx.x;
    const int b  = blockIdx.x >> 6;
    const int i  = blockIdx.x & 63;
    // GEMM1 mapping (4x4 tiles, 16x16 grid)
    const int tx = t & 15, ty = t >> 4;
    const int j0g = ty * 4, r0 = tx * 4;
    // GEMM2/3 mapping (8x8 tiles, 8x32 grid)
    const int tx2 = t & 31, ty2 = t >> 5;
    const int j0 = ty2 * 8, c0 = tx2 * 8;

    extern __shared__ float sm[];
    float* s1  = sm + SM_S1;
    float* s2  = sm + SM_S2;
    float* sP  = sm + SM_SP;
    float* sA  = sm + SM_SA;
    float* sAW = sm + SM_SAW;
    float* sb1 = sm + SM_SB1;
    float* sw2 = sm + SM_SW2;

    const int rowA = b * WW + i;
    sA [t] = g_A [rowA * DD + t];
    sAW[t] = g_AW[rowA * DD + t];
    sb1[t] = att_b1[t];
    sw2[t] = att_w2[t];
    __syncthreads();

    // Fill H^T = (A_i * Bt)^T into s1 and rela^T into s2 (d-major).
    #pragma unroll 4
    for (int it = 0; it < 16; ++it) {
        const int f = it * 256 + t;
        const int d = f >> 4;
        const int c = (f & 15) * 4;
        float4 bv = *(const float4*)&g_BtT[(size_t)b * DD * VV + d * 64 + c];
        const float sa = sA[d];
        bv.x *= sa; bv.y *= sa; bv.z *= sa; bv.w *= sa;
        *(float4*)&s1[d * PAD + c] = bv;
        *(float4*)&s2[d * PAD + c] = *(const float4*)&g_relaT[d * 64 + c];
    }
    __syncthreads();

    // ---- GEMM1: S = H @ rela^T (64x64, K=256) ----
    ull c1[4][2];
    #pragma unroll
    for (int u = 0; u < 4; ++u) { c1[u][0] = 0ull; c1[u][1] = 0ull; }
    #pragma unroll 4
    for (int d = 0; d < DD; ++d) {
        const float4 h4 = *(const float4*)&s1[d * PAD + j0g];
        const ulonglong2 r2 = *(const ulonglong2*)&s2[d * PAD + r0];
        const ull hp[4] = {pack2(h4.x), pack2(h4.y), pack2(h4.z), pack2(h4.w)};
        #pragma unroll
        for (int u = 0; u < 4; ++u) {
            c1[u][0] = fma2(hp[u], r2.x, c1[u][0]);
            c1[u][1] = fma2(hp[u], r2.y, c1[u][1]);
        }
    }
    #pragma unroll
    for (int u = 0; u < 4; ++u) {
        const float2 lo = unpack2(c1[u][0]);
        const float2 hi = unpack2(c1[u][1]);
        *(float4*)&sP[(j0g + u) * PAD + r0] = make_float4(lo.x, lo.y, hi.x, hi.y);
    }
    __syncthreads();

    // Kick off async loads: RW -> s2 lo, att_w1 chunk0 -> s2 hi (overlaps softmax)
    {
        const uint32_t dlo = smem_u32(s2) + (uint32_t)t * 16;
        const uint32_t dhi = smem_u32(s2 + 16384) + (uint32_t)t * 16;
        const float4* rw = (const float4*)g_RW;
        const float4* w1 = (const float4*)att_w1;
        #pragma unroll
        for (int q = 0; q < 16; ++q) {
            cp_async16(dlo + q * 4096, rw + q * 256 + t);
            cp_async16(dhi + q * 4096, w1 + q * 256 + t);
        }
        CP_COMMIT();
    }

    // ---- mask + row softmax over R (4 threads per row, same warp) ----
    {
        const int j = t >> 2, q = t & 3;
        const float nul = sP[j * PAD + 63];
        float v[16];
        float mx = -1e30f;
        #pragma unroll
        for (int m = 0; m < 16; ++m) {
            float s = sP[j * PAD + q * 16 + m];
            s = (s <= nul) ? -1e10f : s;
            v[m] = s;
            mx = fmaxf(mx, s);
        }
        mx = fmaxf(mx, __shfl_xor_sync(0xffffffffu, mx, 1));
        mx = fmaxf(mx, __shfl_xor_sync(0xffffffffu, mx, 2));
        float se = 0.0f;
        #pragma unroll
        for (int m = 0; m < 16; ++m) { v[m] = expf(v[m] - mx); se += v[m]; }
        se += __shfl_xor_sync(0xffffffffu, se, 1);
        se += __shfl_xor_sync(0xffffffffu, se, 2);
        const float inv = 1.0f / se;
        #pragma unroll
        for (int m = 0; m < 16; ++m) sP[j * PAD + q * 16 + m] = v[m] * inv;
    }
    __syncthreads();

    // write norm_scores
    const size_t ns_base = ((size_t)(b * NN + i * VV)) * RR;
    #pragma unroll
    for (int it = 0; it < 16; ++it) {
        const int l = it * 256 + t;
        const int j = l >> 6, r = l & 63;
        out_ns[ns_base + (size_t)j * RR + r] = sP[j * PAD + r];
    }
    CP_WAIT0();
    __syncthreads();

    // ---- GEMM2: PV = P @ RW (64x256, K=64), 8x8 tiles ----
    ull a2[8][4];
    #pragma unroll
    for (int u = 0; u < 8; ++u)
        #pragma unroll
        for (int e = 0; e < 4; ++e) a2[u][e] = 0ull;

    const float* sRW = s2;
    #pragma unroll 2
    for (int r4 = 0; r4 < 16; ++r4) {
        float4 p[8];
        #pragma unroll
        for (int u = 0; u < 8; ++u)
            p[u] = *(const float4*)&sP[(j0 + u) * PAD + r4 * 4];
        #pragma unroll
        for (int q = 0; q < 4; ++q) {
            const int k = r4 * 4 + q;
            const ulonglong2 wa = *(const ulonglong2*)&sRW[k * DD + c0];
            const ulonglong2 wb = *(const ulonglong2*)&sRW[k * DD + c0 + 4];
            #pragma unroll
            for (int u = 0; u < 8; ++u) {
                const float pv = ((const float*)&p[u])[q];
                const ull pk = pack2(pv);
                a2[u][0] = fma2(pk, wa.x, a2[u][0]);
                a2[u][1] = fma2(pk, wa.y, a2[u][1]);
                a2[u][2] = fma2(pk, wb.x, a2[u][2]);
                a2[u][3] = fma2(pk, wb.y, a2[u][3]);
            }
        }
    }

    // tv epilogue: tanh(AW + BW + PV) -> g_tv and sTv (s1)
    float* sTv = s1;
    const size_t tvBase = ((size_t)(b * NN + i * VV)) * DD;
    const float aw0 = sAW[c0 + 0], aw1v = sAW[c0 + 1], aw2v = sAW[c0 + 2], aw3 = sAW[c0 + 3];
    const float aw4 = sAW[c0 + 4], aw5 = sAW[c0 + 5], aw6 = sAW[c0 + 6], aw7 = sAW[c0 + 7];
    #pragma unroll
    for (int u = 0; u < 8; ++u) {
        const int j = j0 + u;
        const float4 bw0 = *(const float4*)&g_BW[(size_t)(b * VV + j) * DD + c0];
        const float4 bw1 = *(const float4*)&g_BW[(size_t)(b * VV + j) * DD + c0 + 4];
        const float2 e0 = unpack2(a2[u][0]);
        const float2 e1 = unpack2(a2[u][1]);
        const float2 e2 = unpack2(a2[u][2]);
        const float2 e3 = unpack2(a2[u][3]);
        float4 t0, t1;
        t0.x = tanh_fast(e0.x + aw0 + bw0.x);
        t0.y = tanh_fast(e0.y + aw1v + bw0.y);
        t0.z = tanh_fast(e1.x + aw2v + bw0.z);
        t0.w = tanh_fast(e1.y + aw3 + bw0.w);
        t1.x = tanh_fast(e2.x + aw4 + bw1.x);
        t1.y = tanh_fast(e2.y + aw5 + bw1.y);
        t1.z = tanh_fast(e3.x + aw6 + bw1.z);
        t1.w = tanh_fast(e3.y + aw7 + bw1.w);
        *(float4*)&g_tv[tvBase + (size_t)j * DD + c0]     = t0;
        *(float4*)&g_tv[tvBase + (size_t)j * DD + c0 + 4] = t1;
        *(float4*)&sTv[j * PAD2 + c0]     = t0;
        *(float4*)&sTv[j * PAD2 + c0 + 4] = t1;
    }
    __syncthreads();

    // ---- GEMM3: Hid = tv @ att_w1 (64x256, K=256), 8x8 tiles,
    //      4 K-chunks of 64, double-buffered via cp.async ----
    ull a3[8][4];
    #pragma unroll
    for (int u = 0; u < 8; ++u)
        #pragma unroll
        for (int e = 0; e < 4; ++e) a3[u][e] = 0ull;

    for (int kk = 0; kk < 4; ++kk) {
        if (kk < 3) {  // prefetch next chunk into the other buffer
            float* nb = ((kk + 1) & 1) ? s2 : s2 + 16384;
            const uint32_t daddr = smem_u32(nb) + (uint32_t)t * 16;
            const float4* src = (const float4*)(att_w1 + (size_t)(kk + 1) * 16384);
            #pragma unroll
            for (int q = 0; q < 16; ++q)
                cp_async16(daddr + q * 4096, src + q * 256 + t);
            CP_COMMIT();
        }
        const float* wb = (kk & 1) ? s2 : s2 + 16384;

        #pragma unroll 2
        for (int k4 = 0; k4 < 16; ++k4) {
            float4 tvv[8];
            #pragma unroll
            for (int u = 0; u < 8; ++u)
                tvv[u] = *(const float4*)&sTv[(j0 + u) * PAD2 + kk * 64 + k4 * 4];
            #pragma unroll
            for (int q = 0; q < 4; ++q) {
                const int k = k4 * 4 + q;
                const ulonglong2 wa = *(const ulonglong2*)&wb[k * DD + c0];
                const ulonglong2 wc = *(const ulonglong2*)&wb[k * DD + c0 + 4];
                #pragma unroll
                for (int u = 0; u < 8; ++u) {
                    const float pv = ((const float*)&tvv[u])[q];
                    const ull pk = pack2(pv);
                    a3[u][0] = fma2(pk, wa.x, a3[u][0]);
                    a3[u][1] = fma2(pk, wa.y, a3[u][1]);
                    a3[u][2] = fma2(pk, wc.x, a3[u][2]);
                    a3[u][3] = fma2(pk, wc.y, a3[u][3]);
                }
            }
        }
        if (kk < 3) { CP_WAIT0(); __syncthreads(); }
    }

    // ---- epilogue: att[j] = tanh(Hid + b1) . att_w2 + b2 ----
    float patt[8];
    #pragma unroll
    for (int u = 0; u < 8; ++u) {
        float s = 0.0f;
        #pragma unroll
        for (int e = 0; e < 4; ++e) {
            const float2 f = unpack2(a3[u][e]);
            const int col = c0 + e * 2;
            s = fmaf(tanh_fast(f.x + sb1[col]),     sw2[col],     s);
            s = fmaf(tanh_fast(f.y + sb1[col + 1]), sw2[col + 1], s);
        }
        patt[u] = s;
    }
    #pragma unroll
    for (int u = 0; u < 8; ++u) {
        patt[u] += __shfl_xor_sync(0xffffffffu, patt[u], 16);
        patt[u] += __shfl_xor_sync(0xffffffffu, patt[u], 8);
        patt[u] += __shfl_xor_sync(0xffffffffu, patt[u], 4);
        patt[u] += __shfl_xor_sync(0xffffffffu, patt[u], 2);
        patt[u] += __shfl_xor_sync(0xffffffffu, patt[u], 1);
    }
    if (tx2 == 0) {
        const float b2v = att_b2[0];
        #pragma unroll
        for (int u = 0; u < 8; ++u)
            g_att[b * NN + i * VV + j0 + u] = patt[u] + b2v;
    }
}

// ---------------------------------------------------------------------------
// Kernel F1: softmax over N of att per batch; writes att_norms; zeroes g_fuse
// ---------------------------------------------------------------------------
__global__ __launch_bounds__(256) void kAtt(float* __restrict__ out_attn)
{
    const int b = blockIdx.x, t = threadIdx.x;
    __shared__ float red[8];
    float vals[16];
    float mx = -1e30f;
    #pragma unroll
    for (int it = 0; it < 16; ++it) {
        vals[it] = g_att[b * NN + it * 256 + t];
        mx = fmaxf(mx, vals[it]);
    }
    #pragma unroll
    for (int o = 16; o; o >>= 1) mx = fmaxf(mx, __shfl_xor_sync(0xffffffffu, mx, o));
    if ((t & 31) == 0) red[t >> 5] = mx;
    __syncthreads();
    float bm = red[0];
    #pragma unroll
    for (int w = 1; w < 8; ++w) bm = fmaxf(bm, red[w]);
    __syncthreads();

    float s = 0.0f;
    #pragma unroll
    for (int it = 0; it < 16; ++it) { vals[it] = expf(vals[it] - bm); s += vals[it]; }
    #pragma unroll
    for (int o = 16; o; o >>= 1) s += __shfl_xor_sync(0xffffffffu, s, o);
    if ((t & 31) == 0) red[t >> 5] = s;
    __syncthreads();
    float bs = 0.0f;
    #pragma unroll
    for (int w = 0; w < 8; ++w) bs += red[w];
    const float inv = 1.0f / bs;
    #pragma unroll
    for (int it = 0; it < 16; ++it)
        out_attn[b * NN + it * 256 + t] = vals[it] * inv;
    g_fuse[b * DD + t] = 0.0f;
}

// ---------------------------------------------------------------------------
// Kernel F2: fuse = sum_n att_norms[n] * tv[n,:]  (1024 blocks: b x 64 chunks)
// ---------------------------------------------------------------------------
__global__ __launch_bounds__(256) void kFuse(const float* __restrict__ attn)
{
    const int b = blockIdx.x >> 6, ch = blockIdx.x & 63, t = threadIdx.x;
    __shared__ float sa[64];
    const int n0 = ch * 64;
    if (t < 64) sa[t] = attn[b * NN + n0 + t];
    __syncthreads();

    const float* tvp = g_tv + ((size_t)(b * NN + n0)) * DD + t;
    float a0 = 0, a1 = 0, a2 = 0, a3 = 0, a4 = 0, a5 = 0, a6 = 0, a7 = 0;
    #pragma unroll
    for (int n = 0; n < 64; n += 8) {
        a0 = fmaf(sa[n + 0], tvp[(size_t)(n + 0) * DD], a0);
        a1 = fmaf(sa[n + 1], tvp[(size_t)(n + 1) * DD], a1);
        a2 = fmaf(sa[n + 2], tvp[(size_t)(n + 2) * DD], a2);
        a3 = fmaf(sa[n + 3], tvp[(size_t)(n + 3) * DD], a3);
        a4 = fmaf(sa[n + 4], tvp[(size_t)(n + 4) * DD], a4);
        a5 = fmaf(sa[n + 5], tvp[(size_t)(n + 5) * DD], a5);
        a6 = fmaf(sa[n + 6], tvp[(size_t)(n + 6) * DD], a6);
        a7 = fmaf(sa[n + 7], tvp[(size_t)(n + 7) * DD], a7);
    }
    atomicAdd(&g_fuse[b * DD + t], ((a0 + a1) + (a2 + a3)) + ((a4 + a5) + (a6 + a7)));
}

// ---------------------------------------------------------------------------
// Kernel F3: logits[b] = fuse . out_w + out_b
// ---------------------------------------------------------------------------
__global__ __launch_bounds__(256) void kLogits(
    float* __restrict__ out, const float* __restrict__ ow, const float* __restrict__ ob)
{
    const int b = blockIdx.x, t = threadIdx.x;
    __shared__ float red[8];
    float v = g_fuse[b * DD + t] * ow[t];
    #pragma unroll
    for (int o = 16; o; o >>= 1) v += __shfl_xor_sync(0xffffffffu, v, o);
    if ((t & 31) == 0) red[t >> 5] = v;
    __syncthreads();
    if (t == 0) {
        float s = 0.0f;
        #pragma unroll
        for (int w = 0; w < 8; ++w) s += red[w];
        out[b] = s + ob[0];
    }
}

// ---------------------------------------------------------------------------
// Launch
// ---------------------------------------------------------------------------
extern "C" void kernel_launch(void* const* d_in, const int* in_sizes, int n_in,
                              void* d_out, int out_size)
{
    const int*   head = (const int*)d_in[0];
    const int*   tail = (const int*)d_in[1];
    const float* emb  = (const float*)d_in[2];
    const float* rela = (const float*)d_in[3];
    const float* fc_w = (const float*)d_in[4];
    const float* fc_b = (const float*)d_in[5];
    const float* aw1  = (const float*)d_in[6];
    const float* ab1  = (const float*)d_in[7];
    const float* aw2  = (const float*)d_in[8];
    const float* ab2  = (const float*)d_in[9];
    const float* ow   = (const float*)d_in[10];
    const float* ob   = (const float*)d_in[11];

    float* out        = (float*)d_out;
    float* out_logits = out;
    float* out_attn   = out + BB;
    float* out_ns     = out + BB + BB * NN;

    cudaFuncSetAttribute(kMain, cudaFuncAttributeMaxDynamicSharedMemorySize, SMEM_M_BYTES);

    kPre   <<<132,   256>>>(head, tail, emb, rela, fc_w, fc_b);
    kMain  <<<BB*WW, 256, SMEM_M_BYTES>>>(aw1, ab1, aw2, ab2, out_ns);
    kAtt   <<<BB,    256>>>(out_attn);
    kFuse  <<<BB*64, 256>>>(out_attn);
    kLogits<<<BB,    256>>>(out_logits, ow, ob);
}

// round 7
// speedup vs baseline: 1.5999x; 1.2055x over previous
#include <cuda_runtime.h>
#include <cuda_bf16.h>
#include <cstdint>
#include <cstddef>

// Problem constants
#define BB   16
#define WW   64
#define VV   64
#define DD   256
#define RR   64
#define NN   (WW*VV)          // 4096
#define PAD  68               // padded stride for d-major GEMM1 tiles

typedef unsigned long long ull;

// ---------------------------------------------------------------------------
// Scratch (static device globals)
// ---------------------------------------------------------------------------
__device__ float g_A   [BB*WW*DD];
__device__ float g_BtT [BB*DD*VV];
__device__ float g_relaT[DD*RR];
__device__ float g_AW  [BB*WW*DD];
__device__ float g_BW  [BB*VV*DD];
__device__ float g_RW  [RR*DD];
__device__ float g_w1r [DD*DD];              // att_w1 pre-rounded to tf32 (rna)
__device__ float g_tv  [(size_t)BB*NN*DD];   // tuple_vec (64 MB)
__device__ float g_att [BB*NN];
__device__ float g_fuse[BB*DD];

// ---------------------------------------------------------------------------
// helpers
// ---------------------------------------------------------------------------
__device__ __forceinline__ float tanh_fast(float x) {
    float y; asm("tanh.approx.f32 %0, %1;" : "=f"(y) : "f"(x)); return y;
}
__device__ __forceinline__ ull fma2(ull a, ull b, ull c) {
    ull d; asm("fma.rn.f32x2 %0, %1, %2, %3;" : "=l"(d) : "l"(a), "l"(b), "l"(c)); return d;
}
__device__ __forceinline__ ull pack2(float x) {
    ull r; asm("mov.b64 %0, {%1, %1};" : "=l"(r) : "f"(x)); return r;
}
__device__ __forceinline__ float2 unpack2(ull v) {
    float2 f; asm("mov.b64 {%0, %1}, %2;" : "=f"(f.x), "=f"(f.y) : "l"(v)); return f;
}
__device__ __forceinline__ uint32_t tf32_rna(float x) {
    uint32_t r; asm("cvt.rna.tf32.f32 %0, %1;" : "=r"(r) : "f"(x)); return r;
}
__device__ __forceinline__ uint32_t smem_u32(const void* p) {
    uint32_t a;
    asm("{ .reg .u64 tmp; cvta.to.shared.u64 tmp, %1; cvt.u32.u64 %0, tmp; }"
        : "=r"(a) : "l"(p));
    return a;
}
__device__ __forceinline__ void cp_async16(uint32_t daddr, const void* src) {
    asm volatile("cp.async.cg.shared.global [%0], [%1], 16;"
                 :: "r"(daddr), "l"(src) : "memory");
}
#define CP_COMMIT() asm volatile("cp.async.commit_group;" ::: "memory")
#define CP_WAIT0()  asm volatile("cp.async.wait_group 0;" ::: "memory")

// m16n8k8 tf32 MMA (HMMA fallback path on sm_103; not an 'a' feature)
__device__ __forceinline__ void mma_tf32(float c[4],
    uint32_t a0, uint32_t a1, uint32_t a2, uint32_t a3,
    uint32_t b0, uint32_t b1)
{
    asm volatile(
        "mma.sync.aligned.m16n8k8.row.col.f32.tf32.tf32.f32 "
        "{%0,%1,%2,%3}, {%4,%5,%6,%7}, {%8,%9}, {%0,%1,%2,%3};"
        : "+f"(c[0]), "+f"(c[1]), "+f"(c[2]), "+f"(c[3])
        : "r"(a0), "r"(a1), "r"(a2), "r"(a3), "r"(b0), "r"(b1));
}

// split fp32 -> (bf16 hi, bf16 lo), packed into one u32 (hi in high half)
__device__ __forceinline__ uint32_t pack_bf16split(float x) {
    __nv_bfloat16 h = __float2bfloat16_rn(x);
    float hf = __bfloat162float(h);
    __nv_bfloat16 l = __float2bfloat16_rn(x - hf);
    return ((uint32_t)__bfloat16_as_ushort(h) << 16) | (uint32_t)__bfloat16_as_ushort(l);
}

// ---------------------------------------------------------------------------
// Kernel R: round att_w1 to tf32 once (removes HMMA truncation bias)
// ---------------------------------------------------------------------------
__global__ __launch_bounds__(256) void kRnd(const float* __restrict__ aw1)
{
    const int i = (blockIdx.x * 256 + threadIdx.x) * 4;
    const float4 v = *(const float4*)(aw1 + i);
    float4 r;
    r.x = __uint_as_float(tf32_rna(v.x));
    r.y = __uint_as_float(tf32_rna(v.y));
    r.z = __uint_as_float(tf32_rna(v.z));
    r.w = __uint_as_float(tf32_rna(v.w));
    *(float4*)(g_w1r + i) = r;
}

// ---------------------------------------------------------------------------
// Kernel P: gather + AW/BW/RW precompute + transposed copies (132 blocks)
// ---------------------------------------------------------------------------
__global__ __launch_bounds__(256) void kPre(
    const int* __restrict__ head, const int* __restrict__ tail,
    const float* __restrict__ emb, const float* __restrict__ rela,
    const float* __restrict__ fc_w, const float* __restrict__ fc_b)
{
    __shared__ float sX[16][257];
    const int g = blockIdx.x, t = threadIdx.x;
    const int kind = (g < 64) ? 0 : (g < 128 ? 1 : 2);
    const int row0 = ((kind == 0) ? g : (kind == 1) ? (g - 64) : (g - 128)) * 16;

    #pragma unroll 4
    for (int rr = 0; rr < 16; ++rr) {
        const int row = row0 + rr;
        float v;
        if (kind == 0)      v = emb[(size_t)head[row] * DD + t];
        else if (kind == 1) v = emb[(size_t)tail[row] * DD + t];
        else                v = rela[row * DD + t];
        sX[rr][t] = v;
        if (kind == 0)      g_A[row * DD + t] = v;
    }
    __syncthreads();

    const float* Wp = fc_w + (size_t)kind * DD * DD;
    float acc[16];
    #pragma unroll
    for (int r = 0; r < 16; ++r) acc[r] = (kind == 0) ? fc_b[t] : 0.0f;

    #pragma unroll 4
    for (int k = 0; k < DD; ++k) {
        const float wv = Wp[k * DD + t];
        #pragma unroll
        for (int r = 0; r < 16; ++r) acc[r] = fmaf(sX[r][k], wv, acc[r]);
    }

    float* dst = (kind == 0) ? g_AW : (kind == 1) ? g_BW : g_RW;
    #pragma unroll
    for (int r = 0; r < 16; ++r) dst[(row0 + r) * DD + t] = acc[r];

    if (kind != 0) {
        float* dstT = (kind == 1)
            ? (g_BtT + (size_t)(row0 >> 6) * DD * VV + (row0 & 63))
            : (g_relaT + row0);
        #pragma unroll
        for (int it = 0; it < 4; ++it) {
            const int f = it * 256 + t;
            const int d = f >> 2;
            const int q = f & 3;
            float4 v;
            v.x = sX[q * 4 + 0][d];
            v.y = sX[q * 4 + 1][d];
            v.z = sX[q * 4 + 2][d];
            v.w = sX[q * 4 + 3][d];
            *(float4*)&dstT[d * 64 + q * 4] = v;
        }
    }
}

// ---------------------------------------------------------------------------
// Kernel M: fused per (b,i). 1024 blocks x 256 threads.
//   GEMM1 (scalar fp32, 2 k-halves), softmax, GEMM2 (scalar fp32),
//   GEMM3 via mma.sync tf32 split-A (bf16 hi/lo packed), att epilogue.
// smem (float offsets):
//   [0, 17408)       : GEMM1 tiles s1h/s2h [128][68] x2 -> later sApk u32 [64][260]
//   [17408, 34304)   : sW0 [64][264]  (RW linear 256-stride for GEMM2; w1 chunks 264)
//   [34304, 51200)   : sW1 [64][264]
//   [51200, 55552)   : sP [64][68]
//   [55552, ...)     : sA, sAW, sb1, sw2 (256 each), sred (64)
// ---------------------------------------------------------------------------
#define SM_S1    0
#define SM_S2    8704
#define SM_APK   0
#define SM_W0    17408
#define SM_W1    34304
#define SM_SP    51200
#define SM_SA    55552
#define SM_SAW   55808
#define SM_SB1   56064
#define SM_SW2   56320
#define SM_SRED  56576
#define SMEM_M_FLOATS 56640
#define SMEM_M_BYTES  (SMEM_M_FLOATS * 4)

// load one 16KB w1 chunk (64 rows x 256 cols) into smem with 264-float row stride
__device__ __forceinline__ void load_w1_chunk(uint32_t dst_base, const float* src, int t)
{
    #pragma unroll
    for (int q = 0; q < 16; ++q) {
        const int g = q * 256 + t;
        const int row = g >> 6;
        const int c16 = g & 63;
        cp_async16(dst_base + (uint32_t)(row * 1056 + c16 * 16),
                   src + row * 256 + c16 * 4);
    }
}

__global__ __launch_bounds__(256, 1) void kMain(
    const float* __restrict__ att_b1, const float* __restrict__ att_w2,
    const float* __restrict__ att_b2, float* __restrict__ out_ns)
{
    const int t  = threadIdx.x;
    const int b  = blockIdx.x >> 6;
    const int i  = blockIdx.x & 63;
    const int lane = t & 31;
    const int wid  = t >> 5;
    // GEMM1 mapping (4x4 tiles, 16x16 grid)
    const int tx = t & 15, ty = t >> 4;
    const int j0g = ty * 4, r0 = tx * 4;
    // GEMM2 mapping (8x8 tiles, 8x32 grid)
    const int tx2 = t & 31, ty2 = t >> 5;
    const int j0 = ty2 * 8, c0 = tx2 * 8;
    // GEMM3 mma mapping
    const int gid = lane >> 2, tid4 = lane & 3;
    const int wm = (wid & 3) * 16;        // warp m-tile base
    const int wn = (wid >> 2) * 128;      // warp n-half base

    extern __shared__ float sm[];
    float*    s1h  = sm + SM_S1;
    float*    s2h  = sm + SM_S2;
    uint32_t* sApk = (uint32_t*)(sm + SM_APK);
    float*    sW0  = sm + SM_W0;
    float*    sW1  = sm + SM_W1;
    float*    sP   = sm + SM_SP;
    float*    sA   = sm + SM_SA;
    float*    sAW  = sm + SM_SAW;
    float*    sb1  = sm + SM_SB1;
    float*    sw2  = sm + SM_SW2;
    float*    sred = sm + SM_SRED;

    const int rowA = b * WW + i;
    sA [t] = g_A [rowA * DD + t];
    sAW[t] = g_AW[rowA * DD + t];
    sb1[t] = att_b1[t];
    sw2[t] = att_w2[t];
    __syncthreads();

    // ---- GEMM1: S = H @ rela^T (64x64, K=256 in 2 halves of 128) ----
    ull c1[4][2];
    #pragma unroll
    for (int u = 0; u < 4; ++u) { c1[u][0] = 0ull; c1[u][1] = 0ull; }

    for (int half = 0; half < 2; ++half) {
        // fill 128 d-rows of H^T and rela^T
        #pragma unroll 2
        for (int it = 0; it < 8; ++it) {
            const int f = it * 256 + t;       // 2048 float4s
            const int d = f >> 4;
            const int c = (f & 15) * 4;
            const int dg = half * 128 + d;
            float4 bv = *(const float4*)&g_BtT[(size_t)b * DD * VV + dg * 64 + c];
            const float sa = sA[dg];
            bv.x *= sa; bv.y *= sa; bv.z *= sa; bv.w *= sa;
            *(float4*)&s1h[d * PAD + c] = bv;
            *(float4*)&s2h[d * PAD + c] = *(const float4*)&g_relaT[dg * 64 + c];
        }
        __syncthreads();

        #pragma unroll 4
        for (int d = 0; d < 128; ++d) {
            const float4 h4 = *(const float4*)&s1h[d * PAD + j0g];
            const ulonglong2 r2 = *(const ulonglong2*)&s2h[d * PAD + r0];
            const ull hp[4] = {pack2(h4.x), pack2(h4.y), pack2(h4.z), pack2(h4.w)};
            #pragma unroll
            for (int u = 0; u < 4; ++u) {
                c1[u][0] = fma2(hp[u], r2.x, c1[u][0]);
                c1[u][1] = fma2(hp[u], r2.y, c1[u][1]);
            }
        }
        __syncthreads();
    }
    #pragma unroll
    for (int u = 0; u < 4; ++u) {
        const float2 lo = unpack2(c1[u][0]);
        const float2 hi = unpack2(c1[u][1]);
        *(float4*)&sP[(j0g + u) * PAD + r0] = make_float4(lo.x, lo.y, hi.x, hi.y);
    }
    __syncthreads();

    // async: RW -> sW0 (linear, 256 stride), w1 chunk0 -> sW1 (264 stride)
    {
        const uint32_t w0b = smem_u32(sW0) + (uint32_t)t * 16;
        const float4* rw = (const float4*)g_RW;
        #pragma unroll
        for (int q = 0; q < 16; ++q)
            cp_async16(w0b + q * 4096, rw + q * 256 + t);
        load_w1_chunk(smem_u32(sW1), g_w1r, t);
        CP_COMMIT();
    }

    // ---- mask + row softmax over R ----
    {
        const int j = t >> 2, q = t & 3;
        const float nul = sP[j * PAD + 63];
        float v[16];
        float mx = -1e30f;
        #pragma unroll
        for (int m = 0; m < 16; ++m) {
            float s = sP[j * PAD + q * 16 + m];
            s = (s <= nul) ? -1e10f : s;
            v[m] = s;
            mx = fmaxf(mx, s);
        }
        mx = fmaxf(mx, __shfl_xor_sync(0xffffffffu, mx, 1));
        mx = fmaxf(mx, __shfl_xor_sync(0xffffffffu, mx, 2));
        float se = 0.0f;
        #pragma unroll
        for (int m = 0; m < 16; ++m) { v[m] = expf(v[m] - mx); se += v[m]; }
        se += __shfl_xor_sync(0xffffffffu, se, 1);
        se += __shfl_xor_sync(0xffffffffu, se, 2);
        const float inv = 1.0f / se;
        #pragma unroll
        for (int m = 0; m < 16; ++m) sP[j * PAD + q * 16 + m] = v[m] * inv;
    }
    __syncthreads();

    // write norm_scores
    const size_t ns_base = ((size_t)(b * NN + i * VV)) * RR;
    #pragma unroll
    for (int it = 0; it < 16; ++it) {
        const int l = it * 256 + t;
        const int j = l >> 6, r = l & 63;
        out_ns[ns_base + (size_t)j * RR + r] = sP[j * PAD + r];
    }
    CP_WAIT0();
    __syncthreads();

    // ---- GEMM2: PV = P @ RW (64x256, K=64), 8x8 tiles, scalar fp32 ----
    ull a2[8][4];
    #pragma unroll
    for (int u = 0; u < 8; ++u)
        #pragma unroll
        for (int e = 0; e < 4; ++e) a2[u][e] = 0ull;

    #pragma unroll 2
    for (int r4 = 0; r4 < 16; ++r4) {
        float4 p[8];
        #pragma unroll
        for (int u = 0; u < 8; ++u)
            p[u] = *(const float4*)&sP[(j0 + u) * PAD + r4 * 4];
        #pragma unroll
        for (int q = 0; q < 4; ++q) {
            const int k = r4 * 4 + q;
            const ulonglong2 wa = *(const ulonglong2*)&sW0[k * DD + c0];
            const ulonglong2 wb2 = *(const ulonglong2*)&sW0[k * DD + c0 + 4];
            #pragma unroll
            for (int u = 0; u < 8; ++u) {
                const float pv = ((const float*)&p[u])[q];
                const ull pk = pack2(pv);
                a2[u][0] = fma2(pk, wa.x, a2[u][0]);
                a2[u][1] = fma2(pk, wa.y, a2[u][1]);
                a2[u][2] = fma2(pk, wb2.x, a2[u][2]);
                a2[u][3] = fma2(pk, wb2.y, a2[u][3]);
            }
        }
    }

    // tv epilogue: tanh(AW + BW + PV) -> g_tv and packed bf16-split -> sApk
    const size_t tvBase = ((size_t)(b * NN + i * VV)) * DD;
    const float aw[8] = { sAW[c0+0], sAW[c0+1], sAW[c0+2], sAW[c0+3],
                          sAW[c0+4], sAW[c0+5], sAW[c0+6], sAW[c0+7] };
    #pragma unroll
    for (int u = 0; u < 8; ++u) {
        const int j = j0 + u;
        const float4 bw0 = *(const float4*)&g_BW[(size_t)(b * VV + j) * DD + c0];
        const float4 bw1 = *(const float4*)&g_BW[(size_t)(b * VV + j) * DD + c0 + 4];
        const float2 e0 = unpack2(a2[u][0]);
        const float2 e1 = unpack2(a2[u][1]);
        const float2 e2 = unpack2(a2[u][2]);
        const float2 e3 = unpack2(a2[u][3]);
        float4 t0, t1;
        t0.x = tanh_fast(e0.x + aw[0] + bw0.x);
        t0.y = tanh_fast(e0.y + aw[1] + bw0.y);
        t0.z = tanh_fast(e1.x + aw[2] + bw0.z);
        t0.w = tanh_fast(e1.y + aw[3] + bw0.w);
        t1.x = tanh_fast(e2.x + aw[4] + bw1.x);
        t1.y = tanh_fast(e2.y + aw[5] + bw1.y);
        t1.z = tanh_fast(e3.x + aw[6] + bw1.z);
        t1.w = tanh_fast(e3.y + aw[7] + bw1.w);
        *(float4*)&g_tv[tvBase + (size_t)j * DD + c0]     = t0;
        *(float4*)&g_tv[tvBase + (size_t)j * DD + c0 + 4] = t1;
        uint4 pk0, pk1;
        pk0.x = pack_bf16split(t0.x); pk0.y = pack_bf16split(t0.y);
        pk0.z = pack_bf16split(t0.z); pk0.w = pack_bf16split(t0.w);
        pk1.x = pack_bf16split(t1.x); pk1.y = pack_bf16split(t1.y);
        pk1.z = pack_bf16split(t1.z); pk1.w = pack_bf16split(t1.w);
        *(uint4*)&sApk[j * 260 + c0]     = pk0;
        *(uint4*)&sApk[j * 260 + c0 + 4] = pk1;
    }
    __syncthreads();

    // ---- GEMM3: Hid = tv @ w1r via mma.sync tf32 (split-A 2-pass) ----
    // warp: 16 m-rows (wm) x 128 n-cols (wn); K=256 in 4 chunks of 64.
    float acc[16][4];
    #pragma unroll
    for (int nt = 0; nt < 16; ++nt)
        #pragma unroll
        for (int e = 0; e < 4; ++e) acc[nt][e] = 0.0f;

    const int ar0 = (wm + gid) * 260;
    const int ar1 = (wm + gid + 8) * 260;

    for (int kk = 0; kk < 4; ++kk) {
        if (kk < 3) {   // prefetch next chunk into the other buffer
            uint32_t nb = ((kk + 1) & 1) ? smem_u32(sW0) : smem_u32(sW1);
            load_w1_chunk(nb, g_w1r + (size_t)(kk + 1) * 16384, t);
            CP_COMMIT();
        }
        const float* wb = (kk & 1) ? sW0 : sW1;

        #pragma unroll
        for (int ks = 0; ks < 8; ++ks) {
            const int kc = kk * 64 + ks * 8;   // global k base (for A)
            const int kl = ks * 8;             // chunk-local k base (for B)
            const uint32_t pa0 = sApk[ar0 + kc + tid4];
            const uint32_t pa1 = sApk[ar1 + kc + tid4];
            const uint32_t pa2 = sApk[ar0 + kc + tid4 + 4];
            const uint32_t pa3 = sApk[ar1 + kc + tid4 + 4];
            const uint32_t h0 = pa0 & 0xFFFF0000u, l0 = pa0 << 16;
            const uint32_t h1 = pa1 & 0xFFFF0000u, l1 = pa1 << 16;
            const uint32_t h2 = pa2 & 0xFFFF0000u, l2 = pa2 << 16;
            const uint32_t h3 = pa3 & 0xFFFF0000u, l3 = pa3 << 16;
            const float* bk0 = wb + (kl + tid4) * 264 + wn + gid;
            const float* bk1 = wb + (kl + tid4 + 4) * 264 + wn + gid;
            #pragma unroll
            for (int nt = 0; nt < 16; ++nt) {
                const uint32_t b0 = __float_as_uint(bk0[nt * 8]);
                const uint32_t b1 = __float_as_uint(bk1[nt * 8]);
                mma_tf32(acc[nt], h0, h1, h2, h3, b0, b1);
                mma_tf32(acc[nt], l0, l1, l2, l3, b0, b1);
            }
        }
        if (kk < 3) { CP_WAIT0(); __syncthreads(); }
    }

    // ---- epilogue: att[row] = sum_col tanh(hid + b1) * w2 + b2 ----
    float p0 = 0.0f, p1 = 0.0f;
    #pragma unroll
    for (int nt = 0; nt < 16; ++nt) {
        const int col = wn + nt * 8 + 2 * tid4;
        p0 = fmaf(tanh_fast(acc[nt][0] + sb1[col]),     sw2[col],     p0);
        p0 = fmaf(tanh_fast(acc[nt][1] + sb1[col + 1]), sw2[col + 1], p0);
        p1 = fmaf(tanh_fast(acc[nt][2] + sb1[col]),     sw2[col],     p1);
        p1 = fmaf(tanh_fast(acc[nt][3] + sb1[col + 1]), sw2[col + 1], p1);
    }
    // reduce over tid4 (4 lanes cover the warp's 128 cols for each row)
    p0 += __shfl_xor_sync(0xffffffffu, p0, 1);
    p0 += __shfl_xor_sync(0xffffffffu, p0, 2);
    p1 += __shfl_xor_sync(0xffffffffu, p1, 1);
    p1 += __shfl_xor_sync(0xffffffffu, p1, 2);

    if (wid < 4) {
        if (tid4 == 0) { sred[wm + gid] = p0; sred[wm + gid + 8] = p1; }
    }
    __syncthreads();
    if (wid >= 4) {
        if (tid4 == 0) { sred[wm + gid] += p0; sred[wm + gid + 8] += p1; }
    }
    __syncthreads();
    if (t < 64)
        g_att[b * NN + i * VV + t] = sred[t] + att_b2[0];
}

// ---------------------------------------------------------------------------
// Kernel F1: softmax over N of att per batch; writes att_norms; zeroes g_fuse
// ---------------------------------------------------------------------------
__global__ __launch_bounds__(256) void kAtt(float* __restrict__ out_attn)
{
    const int b = blockIdx.x, t = threadIdx.x;
    __shared__ float red[8];
    float vals[16];
    float mx = -1e30f;
    #pragma unroll
    for (int it = 0; it < 16; ++it) {
        vals[it] = g_att[b * NN + it * 256 + t];
        mx = fmaxf(mx, vals[it]);
    }
    #pragma unroll
    for (int o = 16; o; o >>= 1) mx = fmaxf(mx, __shfl_xor_sync(0xffffffffu, mx, o));
    if ((t & 31) == 0) red[t >> 5] = mx;
    __syncthreads();
    float bm = red[0];
    #pragma unroll
    for (int w = 1; w < 8; ++w) bm = fmaxf(bm, red[w]);
    __syncthreads();

    float s = 0.0f;
    #pragma unroll
    for (int it = 0; it < 16; ++it) { vals[it] = expf(vals[it] - bm); s += vals[it]; }
    #pragma unroll
    for (int o = 16; o; o >>= 1) s += __shfl_xor_sync(0xffffffffu, s, o);
    if ((t & 31) == 0) red[t >> 5] = s;
    __syncthreads();
    float bs = 0.0f;
    #pragma unroll
    for (int w = 0; w < 8; ++w) bs += red[w];
    const float inv = 1.0f / bs;
    #pragma unroll
    for (int it = 0; it < 16; ++it)
        out_attn[b * NN + it * 256 + t] = vals[it] * inv;
    g_fuse[b * DD + t] = 0.0f;
}

// ---------------------------------------------------------------------------
// Kernel F2: fuse = sum_n att_norms[n] * tv[n,:]  (1024 blocks)
// ---------------------------------------------------------------------------
__global__ __launch_bounds__(256) void kFuse(const float* __restrict__ attn)
{
    const int b = blockIdx.x >> 6, ch = blockIdx.x & 63, t = threadIdx.x;
    __shared__ float sa[64];
    const int n0 = ch * 64;
    if (t < 64) sa[t] = attn[b * NN + n0 + t];
    __syncthreads();

    const float* tvp = g_tv + ((size_t)(b * NN + n0)) * DD + t;
    float a0 = 0, a1 = 0, a2 = 0, a3 = 0, a4 = 0, a5 = 0, a6 = 0, a7 = 0;
    #pragma unroll
    for (int n = 0; n < 64; n += 8) {
        a0 = fmaf(sa[n + 0], tvp[(size_t)(n + 0) * DD], a0);
        a1 = fmaf(sa[n + 1], tvp[(size_t)(n + 1) * DD], a1);
        a2 = fmaf(sa[n + 2], tvp[(size_t)(n + 2) * DD], a2);
        a3 = fmaf(sa[n + 3], tvp[(size_t)(n + 3) * DD], a3);
        a4 = fmaf(sa[n + 4], tvp[(size_t)(n + 4) * DD], a4);
        a5 = fmaf(sa[n + 5], tvp[(size_t)(n + 5) * DD], a5);
        a6 = fmaf(sa[n + 6], tvp[(size_t)(n + 6) * DD], a6);
        a7 = fmaf(sa[n + 7], tvp[(size_t)(n + 7) * DD], a7);
    }
    atomicAdd(&g_fuse[b * DD + t], ((a0 + a1) + (a2 + a3)) + ((a4 + a5) + (a6 + a7)));
}

// ---------------------------------------------------------------------------
// Kernel F3: logits[b] = fuse . out_w + out_b
// ---------------------------------------------------------------------------
__global__ __launch_bounds__(256) void kLogits(
    float* __restrict__ out, const float* __restrict__ ow, const float* __restrict__ ob)
{
    const int b = blockIdx.x, t = threadIdx.x;
    __shared__ float red[8];
    float v = g_fuse[b * DD + t] * ow[t];
    #pragma unroll
    for (int o = 16; o; o >>= 1) v += __shfl_xor_sync(0xffffffffu, v, o);
    if ((t & 31) == 0) red[t >> 5] = v;
    __syncthreads();
    if (t == 0) {
        float s = 0.0f;
        #pragma unroll
        for (int w = 0; w < 8; ++w) s += red[w];
        out[b] = s + ob[0];
    }
}

// ---------------------------------------------------------------------------
// Launch
// ---------------------------------------------------------------------------
extern "C" void kernel_launch(void* const* d_in, const int* in_sizes, int n_in,
                              void* d_out, int out_size)
{
    const int*   head = (const int*)d_in[0];
    const int*   tail = (const int*)d_in[1];
    const float* emb  = (const float*)d_in[2];
    const float* rela = (const float*)d_in[3];
    const float* fc_w = (const float*)d_in[4];
    const float* fc_b = (const float*)d_in[5];
    const float* aw1  = (const float*)d_in[6];
    const float* ab1  = (const float*)d_in[7];
    const float* aw2  = (const float*)d_in[8];
    const float* ab2  = (const float*)d_in[9];
    const float* ow   = (const float*)d_in[10];
    const float* ob   = (const float*)d_in[11];

    float* out        = (float*)d_out;
    float* out_logits = out;
    float* out_attn   = out + BB;
    float* out_ns     = out + BB + BB * NN;

    cudaFuncSetAttribute(kMain, cudaFuncAttributeMaxDynamicSharedMemorySize, SMEM_M_BYTES);

    kPre   <<<132,   256>>>(head, tail, emb, rela, fc_w, fc_b);
    kRnd   <<<64,    256>>>(aw1);
    kMain  <<<BB*WW, 256, SMEM_M_BYTES>>>(ab1, aw2, ab2, out_ns);
    kAtt   <<<BB,    256>>>(out_attn);
    kFuse  <<<BB*64, 256>>>(out_attn);
    kLogits<<<BB,    256>>>(out_logits, ow, ob);
}

// round 8
// speedup vs baseline: 2.1330x; 1.3332x over previous
#include <cuda_runtime.h>
#include <cuda_bf16.h>
#include <cstdint>
#include <cstddef>

// Problem constants
#define BB   16
#define WW   64
#define VV   64
#define DD   256
#define RR   64
#define NN   (WW*VV)          // 4096
#define PAD  68               // padded stride for d-major GEMM1 tiles

typedef unsigned long long ull;

// ---------------------------------------------------------------------------
// Scratch (static device globals)
// ---------------------------------------------------------------------------
__device__ float g_A   [BB*WW*DD];
__device__ float g_BtT [BB*DD*VV];
__device__ float g_relaT[DD*RR];
__device__ float g_AW  [BB*WW*DD];
__device__ float g_BW  [BB*VV*DD];
__device__ float g_RW  [RR*DD];
__device__ uint32_t g_w1bT[DD*DD/2];             // w1^T bf16 pairs: [n][kpair]
__device__ __nv_bfloat16 g_tvh[(size_t)BB*NN*DD]; // tuple_vec bf16 (32 MB)
__device__ float g_att [BB*NN];
__device__ float g_fuse[BB*DD];

// ---------------------------------------------------------------------------
// helpers
// ---------------------------------------------------------------------------
__device__ __forceinline__ float tanh_fast(float x) {
    float y; asm("tanh.approx.f32 %0, %1;" : "=f"(y) : "f"(x)); return y;
}
__device__ __forceinline__ ull fma2(ull a, ull b, ull c) {
    ull d; asm("fma.rn.f32x2 %0, %1, %2, %3;" : "=l"(d) : "l"(a), "l"(b), "l"(c)); return d;
}
__device__ __forceinline__ ull pack2(float x) {
    ull r; asm("mov.b64 %0, {%1, %1};" : "=l"(r) : "f"(x)); return r;
}
__device__ __forceinline__ float2 unpack2(ull v) {
    float2 f; asm("mov.b64 {%0, %1}, %2;" : "=f"(f.x), "=f"(f.y) : "l"(v)); return f;
}
__device__ __forceinline__ uint32_t smem_u32(const void* p) {
    uint32_t a;
    asm("{ .reg .u64 tmp; cvta.to.shared.u64 tmp, %1; cvt.u32.u64 %0, tmp; }"
        : "=r"(a) : "l"(p));
    return a;
}
__device__ __forceinline__ void cp_async16(uint32_t daddr, const void* src) {
    asm volatile("cp.async.cg.shared.global [%0], [%1], 16;"
                 :: "r"(daddr), "l"(src) : "memory");
}
#define CP_COMMIT() asm volatile("cp.async.commit_group;" ::: "memory")
#define CP_WAIT0()  asm volatile("cp.async.wait_group 0;" ::: "memory")

// m16n8k16 bf16 MMA (HMMA path; available since sm_80, not an 'a' feature)
__device__ __forceinline__ void mma_bf16(float c[4],
    uint32_t a0, uint32_t a1, uint32_t a2, uint32_t a3,
    uint32_t b0, uint32_t b1)
{
    asm volatile(
        "mma.sync.aligned.m16n8k16.row.col.f32.bf16.bf16.f32 "
        "{%0,%1,%2,%3}, {%4,%5,%6,%7}, {%8,%9}, {%0,%1,%2,%3};"
        : "+f"(c[0]), "+f"(c[1]), "+f"(c[2]), "+f"(c[3])
        : "r"(a0), "r"(a1), "r"(a2), "r"(a3), "r"(b0), "r"(b1));
}

// pack two floats into a bf16x2 u32 (low = first elem)
__device__ __forceinline__ uint32_t pkbf2(float a, float b) {
    return (uint32_t)__bfloat16_as_ushort(__float2bfloat16_rn(a))
         | ((uint32_t)__bfloat16_as_ushort(__float2bfloat16_rn(b)) << 16);
}
__device__ __forceinline__ float bf16hi_f(float x) {
    return __bfloat162float(__float2bfloat16_rn(x));
}

// ---------------------------------------------------------------------------
// Kernel W: build g_w1bT = att_w1^T as bf16 pairs. w1bT[n][p] packs
// (w1[2p][n], w1[2p+1][n]). Grid 128 (pair rows), 256 threads (n).
// ---------------------------------------------------------------------------
__global__ __launch_bounds__(256) void kW1T(const float* __restrict__ aw1)
{
    const int p = blockIdx.x;
    const int n = threadIdx.x;
    const float a = aw1[(2 * p) * DD + n];
    const float b = aw1[(2 * p + 1) * DD + n];
    g_w1bT[n * 128 + p] = pkbf2(a, b);
}

// ---------------------------------------------------------------------------
// Kernel P: gather + AW/BW/RW precompute + transposed copies (132 blocks)
// ---------------------------------------------------------------------------
__global__ __launch_bounds__(256) void kPre(
    const int* __restrict__ head, const int* __restrict__ tail,
    const float* __restrict__ emb, const float* __restrict__ rela,
    const float* __restrict__ fc_w, const float* __restrict__ fc_b)
{
    __shared__ float sX[16][257];
    const int g = blockIdx.x, t = threadIdx.x;
    const int kind = (g < 64) ? 0 : (g < 128 ? 1 : 2);
    const int row0 = ((kind == 0) ? g : (kind == 1) ? (g - 64) : (g - 128)) * 16;

    #pragma unroll 4
    for (int rr = 0; rr < 16; ++rr) {
        const int row = row0 + rr;
        float v;
        if (kind == 0)      v = emb[(size_t)head[row] * DD + t];
        else if (kind == 1) v = emb[(size_t)tail[row] * DD + t];
        else                v = rela[row * DD + t];
        sX[rr][t] = v;
        if (kind == 0)      g_A[row * DD + t] = v;
    }
    __syncthreads();

    const float* Wp = fc_w + (size_t)kind * DD * DD;
    float acc[16];
    #pragma unroll
    for (int r = 0; r < 16; ++r) acc[r] = (kind == 0) ? fc_b[t] : 0.0f;

    #pragma unroll 4
    for (int k = 0; k < DD; ++k) {
        const float wv = Wp[k * DD + t];
        #pragma unroll
        for (int r = 0; r < 16; ++r) acc[r] = fmaf(sX[r][k], wv, acc[r]);
    }

    float* dst = (kind == 0) ? g_AW : (kind == 1) ? g_BW : g_RW;
    #pragma unroll
    for (int r = 0; r < 16; ++r) dst[(row0 + r) * DD + t] = acc[r];

    if (kind != 0) {
        float* dstT = (kind == 1)
            ? (g_BtT + (size_t)(row0 >> 6) * DD * VV + (row0 & 63))
            : (g_relaT + row0);
        #pragma unroll
        for (int it = 0; it < 4; ++it) {
            const int f = it * 256 + t;
            const int d = f >> 2;
            const int q = f & 3;
            float4 v;
            v.x = sX[q * 4 + 0][d];
            v.y = sX[q * 4 + 1][d];
            v.z = sX[q * 4 + 2][d];
            v.w = sX[q * 4 + 3][d];
            *(float4*)&dstT[d * 64 + q * 4] = v;
        }
    }
}

// ---------------------------------------------------------------------------
// Kernel M: fused per (b,i). 1024 blocks x 256 threads.
//   GEMM1 (scalar fp32), softmax, GEMM2 (scalar fp32),
//   GEMM3 via mma.sync m16n8k16 bf16 split-A, att epilogue.
// smem layout (float offsets):
//   [0, 17408)       : GEMM1 tiles [128][68]x2 -> later sAhi/sAlo u32 [64][132]x2
//   [17408, 33792)   : sRW [64][256]
//   [33792, 52224)   : w1 bf16 buffers: 2 x u32[256][36]
//   [52224, 56576)   : sP [64][68]
//   [56576, ...)     : sA, sAW, sb1, sw2 (256 each), sred (64)
// ---------------------------------------------------------------------------
#define SM_S1    0
#define SM_S2    8704
#define SM_APK   0
#define SM_RW    17408
#define SM_WB    33792
#define SM_SP    52224
#define SM_SA    56576
#define SM_SAW   56832
#define SM_SB1   57088
#define SM_SW2   57344
#define SM_SRED  57600
#define SMEM_M_FLOATS 57664
#define SMEM_M_BYTES  (SMEM_M_FLOATS * 4)

// load one w1 bf16 chunk: smem[n][q] = g_w1bT[n][kk*32+q], n<256, q<32, stride 36
__device__ __forceinline__ void load_w1_chunk(uint32_t dst_base, int kk, int t)
{
    const uint32_t* src = g_w1bT + kk * 32;
    #pragma unroll
    for (int it = 0; it < 8; ++it) {
        const int idx = it * 256 + t;      // 2048 uint4s
        const int n  = idx >> 3;
        const int q4 = (idx & 7) * 4;
        cp_async16(dst_base + (uint32_t)(n * 144 + q4 * 4), src + n * 128 + q4);
    }
}

__global__ __launch_bounds__(256, 1) void kMain(
    const float* __restrict__ att_b1, const float* __restrict__ att_w2,
    const float* __restrict__ att_b2, float* __restrict__ out_ns)
{
    const int t  = threadIdx.x;
    const int b  = blockIdx.x >> 6;
    const int i  = blockIdx.x & 63;
    const int lane = t & 31;
    const int wid  = t >> 5;
    // GEMM1 mapping (4x4 tiles, 16x16 grid)
    const int tx = t & 15, ty = t >> 4;
    const int j0g = ty * 4, r0 = tx * 4;
    // GEMM2 mapping (8x8 tiles, 8x32 grid)
    const int tx2 = t & 31, ty2 = t >> 5;
    const int j0 = ty2 * 8, c0 = tx2 * 8;
    // GEMM3 mma mapping
    const int gid = lane >> 2, tid4 = lane & 3;
    const int wm = (wid & 3) * 16;        // warp m-tile base
    const int wn = (wid >> 2) * 128;      // warp n-half base

    extern __shared__ float sm[];
    float*    s1h  = sm + SM_S1;
    float*    s2h  = sm + SM_S2;
    uint32_t* sAhi = (uint32_t*)(sm + SM_APK);        // [64][132]
    uint32_t* sAlo = sAhi + 64 * 132;                  // [64][132]
    float*    sRW  = sm + SM_RW;
    uint32_t* sWB  = (uint32_t*)(sm + SM_WB);          // 2 x [256][36]
    float*    sP   = sm + SM_SP;
    float*    sA   = sm + SM_SA;
    float*    sAW  = sm + SM_SAW;
    float*    sb1  = sm + SM_SB1;
    float*    sw2  = sm + SM_SW2;
    float*    sred = sm + SM_SRED;

    const int rowA = b * WW + i;
    sA [t] = g_A [rowA * DD + t];
    sAW[t] = g_AW[rowA * DD + t];
    sb1[t] = att_b1[t];
    sw2[t] = att_w2[t];
    __syncthreads();

    // ---- GEMM1: S = H @ rela^T (64x64, K=256 in 2 halves of 128) ----
    ull c1[4][2];
    #pragma unroll
    for (int u = 0; u < 4; ++u) { c1[u][0] = 0ull; c1[u][1] = 0ull; }

    for (int half = 0; half < 2; ++half) {
        #pragma unroll 2
        for (int it = 0; it < 8; ++it) {
            const int f = it * 256 + t;       // 2048 float4s
            const int d = f >> 4;
            const int c = (f & 15) * 4;
            const int dg = half * 128 + d;
            float4 bv = *(const float4*)&g_BtT[(size_t)b * DD * VV + dg * 64 + c];
            const float sa = sA[dg];
            bv.x *= sa; bv.y *= sa; bv.z *= sa; bv.w *= sa;
            *(float4*)&s1h[d * PAD + c] = bv;
            *(float4*)&s2h[d * PAD + c] = *(const float4*)&g_relaT[dg * 64 + c];
        }
        __syncthreads();

        #pragma unroll 4
        for (int d = 0; d < 128; ++d) {
            const float4 h4 = *(const float4*)&s1h[d * PAD + j0g];
            const ulonglong2 r2 = *(const ulonglong2*)&s2h[d * PAD + r0];
            const ull hp[4] = {pack2(h4.x), pack2(h4.y), pack2(h4.z), pack2(h4.w)};
            #pragma unroll
            for (int u = 0; u < 4; ++u) {
                c1[u][0] = fma2(hp[u], r2.x, c1[u][0]);
                c1[u][1] = fma2(hp[u], r2.y, c1[u][1]);
            }
        }
        __syncthreads();
    }
    #pragma unroll
    for (int u = 0; u < 4; ++u) {
        const float2 lo = unpack2(c1[u][0]);
        const float2 hi = unpack2(c1[u][1]);
        *(float4*)&sP[(j0g + u) * PAD + r0] = make_float4(lo.x, lo.y, hi.x, hi.y);
    }
    __syncthreads();

    // async: RW -> sRW (linear 256 stride), w1 bf16 chunk0 -> sWB buf0
    {
        const uint32_t rwb = smem_u32(sRW) + (uint32_t)t * 16;
        const float4* rw = (const float4*)g_RW;
        #pragma unroll
        for (int q = 0; q < 16; ++q)
            cp_async16(rwb + q * 4096, rw + q * 256 + t);
        load_w1_chunk(smem_u32(sWB), 0, t);
        CP_COMMIT();
    }

    // ---- mask + row softmax over R ----
    {
        const int j = t >> 2, q = t & 3;
        const float nul = sP[j * PAD + 63];
        float v[16];
        float mx = -1e30f;
        #pragma unroll
        for (int m = 0; m < 16; ++m) {
            float s = sP[j * PAD + q * 16 + m];
            s = (s <= nul) ? -1e10f : s;
            v[m] = s;
            mx = fmaxf(mx, s);
        }
        mx = fmaxf(mx, __shfl_xor_sync(0xffffffffu, mx, 1));
        mx = fmaxf(mx, __shfl_xor_sync(0xffffffffu, mx, 2));
        float se = 0.0f;
        #pragma unroll
        for (int m = 0; m < 16; ++m) { v[m] = expf(v[m] - mx); se += v[m]; }
        se += __shfl_xor_sync(0xffffffffu, se, 1);
        se += __shfl_xor_sync(0xffffffffu, se, 2);
        const float inv = 1.0f / se;
        #pragma unroll
        for (int m = 0; m < 16; ++m) sP[j * PAD + q * 16 + m] = v[m] * inv;
    }
    __syncthreads();

    // write norm_scores
    const size_t ns_base = ((size_t)(b * NN + i * VV)) * RR;
    #pragma unroll
    for (int it = 0; it < 16; ++it) {
        const int l = it * 256 + t;
        const int j = l >> 6, r = l & 63;
        out_ns[ns_base + (size_t)j * RR + r] = sP[j * PAD + r];
    }
    CP_WAIT0();
    __syncthreads();

    // ---- GEMM2: PV = P @ RW (64x256, K=64), 8x8 tiles, scalar fp32 ----
    ull a2[8][4];
    #pragma unroll
    for (int u = 0; u < 8; ++u)
        #pragma unroll
        for (int e = 0; e < 4; ++e) a2[u][e] = 0ull;

    #pragma unroll 2
    for (int r4 = 0; r4 < 16; ++r4) {
        float4 p[8];
        #pragma unroll
        for (int u = 0; u < 8; ++u)
            p[u] = *(const float4*)&sP[(j0 + u) * PAD + r4 * 4];
        #pragma unroll
        for (int q = 0; q < 4; ++q) {
            const int k = r4 * 4 + q;
            const ulonglong2 wa = *(const ulonglong2*)&sRW[k * DD + c0];
            const ulonglong2 wb2 = *(const ulonglong2*)&sRW[k * DD + c0 + 4];
            #pragma unroll
            for (int u = 0; u < 8; ++u) {
                const float pv = ((const float*)&p[u])[q];
                const ull pk = pack2(pv);
                a2[u][0] = fma2(pk, wa.x, a2[u][0]);
                a2[u][1] = fma2(pk, wa.y, a2[u][1]);
                a2[u][2] = fma2(pk, wb2.x, a2[u][2]);
                a2[u][3] = fma2(pk, wb2.y, a2[u][3]);
            }
        }
    }

    // tv epilogue: tanh(AW + BW + PV) -> g_tvh (bf16) and bf16 hi/lo -> sAhi/sAlo
    const size_t tvBase = ((size_t)(b * NN + i * VV)) * DD;
    const float aw[8] = { sAW[c0+0], sAW[c0+1], sAW[c0+2], sAW[c0+3],
                          sAW[c0+4], sAW[c0+5], sAW[c0+6], sAW[c0+7] };
    #pragma unroll
    for (int u = 0; u < 8; ++u) {
        const int j = j0 + u;
        const float4 bw0 = *(const float4*)&g_BW[(size_t)(b * VV + j) * DD + c0];
        const float4 bw1 = *(const float4*)&g_BW[(size_t)(b * VV + j) * DD + c0 + 4];
        const float2 e0 = unpack2(a2[u][0]);
        const float2 e1 = unpack2(a2[u][1]);
        const float2 e2 = unpack2(a2[u][2]);
        const float2 e3 = unpack2(a2[u][3]);
        float v[8];
        v[0] = tanh_fast(e0.x + aw[0] + bw0.x);
        v[1] = tanh_fast(e0.y + aw[1] + bw0.y);
        v[2] = tanh_fast(e1.x + aw[2] + bw0.z);
        v[3] = tanh_fast(e1.y + aw[3] + bw0.w);
        v[4] = tanh_fast(e2.x + aw[4] + bw1.x);
        v[5] = tanh_fast(e2.y + aw[5] + bw1.y);
        v[6] = tanh_fast(e3.x + aw[6] + bw1.z);
        v[7] = tanh_fast(e3.y + aw[7] + bw1.w);
        uint4 hi, lo;
        hi.x = pkbf2(v[0], v[1]); hi.y = pkbf2(v[2], v[3]);
        hi.z = pkbf2(v[4], v[5]); hi.w = pkbf2(v[6], v[7]);
        lo.x = pkbf2(v[0] - bf16hi_f(v[0]), v[1] - bf16hi_f(v[1]));
        lo.y = pkbf2(v[2] - bf16hi_f(v[2]), v[3] - bf16hi_f(v[3]));
        lo.z = pkbf2(v[4] - bf16hi_f(v[4]), v[5] - bf16hi_f(v[5]));
        lo.w = pkbf2(v[6] - bf16hi_f(v[6]), v[7] - bf16hi_f(v[7]));
        *(uint4*)&g_tvh[tvBase + (size_t)j * DD + c0] = hi;   // bf16 copy for kFuse
        *(uint4*)&sAhi[j * 132 + (c0 >> 1)] = hi;
        *(uint4*)&sAlo[j * 132 + (c0 >> 1)] = lo;
    }
    __syncthreads();

    // ---- GEMM3: Hid = tv @ w1 via mma.sync m16n8k16 bf16 (split-A 2-pass) ----
    float acc[16][4];
    #pragma unroll
    for (int nt = 0; nt < 16; ++nt)
        #pragma unroll
        for (int e = 0; e < 4; ++e) acc[nt][e] = 0.0f;

    const int ar0 = (wm + gid) * 132;
    const int ar1 = (wm + gid + 8) * 132;

    for (int kk = 0; kk < 4; ++kk) {
        if (kk < 3) {   // prefetch next chunk into the other buffer
            load_w1_chunk(smem_u32(sWB + ((kk + 1) & 1) * 9216), kk + 1, t);
            CP_COMMIT();
        }
        const uint32_t* wb = sWB + (kk & 1) * 9216;

        #pragma unroll
        for (int ks = 0; ks < 4; ++ks) {        // k16 steps within 64-k chunk
            const int gp = kk * 32 + ks * 8 + tid4;  // global A pair index
            const uint32_t h0 = sAhi[ar0 + gp],     l0 = sAlo[ar0 + gp];
            const uint32_t h1 = sAhi[ar1 + gp],     l1 = sAlo[ar1 + gp];
            const uint32_t h2 = sAhi[ar0 + gp + 4], l2 = sAlo[ar0 + gp + 4];
            const uint32_t h3 = sAhi[ar1 + gp + 4], l3 = sAlo[ar1 + gp + 4];
            const int bq = ks * 8 + tid4;            // chunk-local B pair index
            #pragma unroll
            for (int nt = 0; nt < 16; ++nt) {
                const int n = wn + nt * 8 + gid;
                const uint32_t b0 = wb[n * 36 + bq];
                const uint32_t b1 = wb[n * 36 + bq + 4];
                mma_bf16(acc[nt], h0, h1, h2, h3, b0, b1);
                mma_bf16(acc[nt], l0, l1, l2, l3, b0, b1);
            }
        }
        if (kk < 3) { CP_WAIT0(); __syncthreads(); }
    }

    // ---- epilogue: att[row] = sum_col tanh(hid + b1) * w2 + b2 ----
    float p0 = 0.0f, p1 = 0.0f;
    #pragma unroll
    for (int nt = 0; nt < 16; ++nt) {
        const int col = wn + nt * 8 + 2 * tid4;
        p0 = fmaf(tanh_fast(acc[nt][0] + sb1[col]),     sw2[col],     p0);
        p0 = fmaf(tanh_fast(acc[nt][1] + sb1[col + 1]), sw2[col + 1], p0);
        p1 = fmaf(tanh_fast(acc[nt][2] + sb1[col]),     sw2[col],     p1);
        p1 = fmaf(tanh_fast(acc[nt][3] + sb1[col + 1]), sw2[col + 1], p1);
    }
    p0 += __shfl_xor_sync(0xffffffffu, p0, 1);
    p0 += __shfl_xor_sync(0xffffffffu, p0, 2);
    p1 += __shfl_xor_sync(0xffffffffu, p1, 1);
    p1 += __shfl_xor_sync(0xffffffffu, p1, 2);

    if (wid < 4) {
        if (tid4 == 0) { sred[wm + gid] = p0; sred[wm + gid + 8] = p1; }
    }
    __syncthreads();
    if (wid >= 4) {
        if (tid4 == 0) { sred[wm + gid] += p0; sred[wm + gid + 8] += p1; }
    }
    __syncthreads();
    if (t < 64)
        g_att[b * NN + i * VV + t] = sred[t] + att_b2[0];
}

// ---------------------------------------------------------------------------
// Kernel F1: softmax over N of att per batch; writes att_norms; zeroes g_fuse
// ---------------------------------------------------------------------------
__global__ __launch_bounds__(256) void kAtt(float* __restrict__ out_attn)
{
    const int b = blockIdx.x, t = threadIdx.x;
    __shared__ float red[8];
    float vals[16];
    float mx = -1e30f;
    #pragma unroll
    for (int it = 0; it < 16; ++it) {
        vals[it] = g_att[b * NN + it * 256 + t];
        mx = fmaxf(mx, vals[it]);
    }
    #pragma unroll
    for (int o = 16; o; o >>= 1) mx = fmaxf(mx, __shfl_xor_sync(0xffffffffu, mx, o));
    if ((t & 31) == 0) red[t >> 5] = mx;
    __syncthreads();
    float bm = red[0];
    #pragma unroll
    for (int w = 1; w < 8; ++w) bm = fmaxf(bm, red[w]);
    __syncthreads();

    float s = 0.0f;
    #pragma unroll
    for (int it = 0; it < 16; ++it) { vals[it] = expf(vals[it] - bm); s += vals[it]; }
    #pragma unroll
    for (int o = 16; o; o >>= 1) s += __shfl_xor_sync(0xffffffffu, s, o);
    if ((t & 31) == 0) red[t >> 5] = s;
    __syncthreads();
    float bs = 0.0f;
    #pragma unroll
    for (int w = 0; w < 8; ++w) bs += red[w];
    const float inv = 1.0f / bs;
    #pragma unroll
    for (int it = 0; it < 16; ++it)
        out_attn[b * NN + it * 256 + t] = vals[it] * inv;
    g_fuse[b * DD + t] = 0.0f;
}

// ---------------------------------------------------------------------------
// Kernel F2: fuse = sum_n att_norms[n] * tv[n,:]  (1024 blocks, bf16 tv)
// ---------------------------------------------------------------------------
__global__ __launch_bounds__(256) void kFuse(const float* __restrict__ attn)
{
    const int b = blockIdx.x >> 6, ch = blockIdx.x & 63, t = threadIdx.x;
    __shared__ float sa[64];
    const int n0 = ch * 64;
    if (t < 64) sa[t] = attn[b * NN + n0 + t];
    __syncthreads();

    const __nv_bfloat16* tvp = g_tvh + ((size_t)(b * NN + n0)) * DD + t;
    float a0 = 0, a1 = 0, a2 = 0, a3 = 0, a4 = 0, a5 = 0, a6 = 0, a7 = 0;
    #pragma unroll
    for (int n = 0; n < 64; n += 8) {
        a0 = fmaf(sa[n + 0], __bfloat162float(tvp[(size_t)(n + 0) * DD]), a0);
        a1 = fmaf(sa[n + 1], __bfloat162float(tvp[(size_t)(n + 1) * DD]), a1);
        a2 = fmaf(sa[n + 2], __bfloat162float(tvp[(size_t)(n + 2) * DD]), a2);
        a3 = fmaf(sa[n + 3], __bfloat162float(tvp[(size_t)(n + 3) * DD]), a3);
        a4 = fmaf(sa[n + 4], __bfloat162float(tvp[(size_t)(n + 4) * DD]), a4);
        a5 = fmaf(sa[n + 5], __bfloat162float(tvp[(size_t)(n + 5) * DD]), a5);
        a6 = fmaf(sa[n + 6], __bfloat162float(tvp[(size_t)(n + 6) * DD]), a6);
        a7 = fmaf(sa[n + 7], __bfloat162float(tvp[(size_t)(n + 7) * DD]), a7);
    }
    atomicAdd(&g_fuse[b * DD + t], ((a0 + a1) + (a2 + a3)) + ((a4 + a5) + (a6 + a7)));
}

// ---------------------------------------------------------------------------
// Kernel F3: logits[b] = fuse . out_w + out_b
// ---------------------------------------------------------------------------
__global__ __launch_bounds__(256) void kLogits(
    float* __restrict__ out, const float* __restrict__ ow, const float* __restrict__ ob)
{
    const int b = blockIdx.x, t = threadIdx.x;
    __shared__ float red[8];
    float v = g_fuse[b * DD + t] * ow[t];
    #pragma unroll
    for (int o = 16; o; o >>= 1) v += __shfl_xor_sync(0xffffffffu, v, o);
    if ((t & 31) == 0) red[t >> 5] = v;
    __syncthreads();
    if (t == 0) {
        float s = 0.0f;
        #pragma unroll
        for (int w = 0; w < 8; ++w) s += red[w];
        out[b] = s + ob[0];
    }
}

// ---------------------------------------------------------------------------
// Launch
// ---------------------------------------------------------------------------
extern "C" void kernel_launch(void* const* d_in, const int* in_sizes, int n_in,
                              void* d_out, int out_size)
{
    const int*   head = (const int*)d_in[0];
    const int*   tail = (const int*)d_in[1];
    const float* emb  = (const float*)d_in[2];
    const float* rela = (const float*)d_in[3];
    const float* fc_w = (const float*)d_in[4];
    const float* fc_b = (const float*)d_in[5];
    const float* aw1  = (const float*)d_in[6];
    const float* ab1  = (const float*)d_in[7];
    const float* aw2  = (const float*)d_in[8];
    const float* ab2  = (const float*)d_in[9];
    const float* ow   = (const float*)d_in[10];
    const float* ob   = (const float*)d_in[11];

    float* out        = (float*)d_out;
    float* out_logits = out;
    float* out_attn   = out + BB;
    float* out_ns     = out + BB + BB * NN;

    cudaFuncSetAttribute(kMain, cudaFuncAttributeMaxDynamicSharedMemorySize, SMEM_M_BYTES);

    kPre   <<<132,   256>>>(head, tail, emb, rela, fc_w, fc_b);
    kW1T   <<<128,   256>>>(aw1);
    kMain  <<<BB*WW, 256, SMEM_M_BYTES>>>(ab1, aw2, ab2, out_ns);
    kAtt   <<<BB,    256>>>(out_attn);
    kFuse  <<<BB*64, 256>>>(out_attn);
    kLogits<<<BB,    256>>>(out_logits, ow, ob);
}

// round 9
// speedup vs baseline: 2.2275x; 1.0443x over previous
#include <cuda_runtime.h>
#include <cuda_bf16.h>
#include <cstdint>
#include <cstddef>

// Problem constants
#define BB   16
#define WW   64
#define VV   64
#define DD   256
#define RR   64
#define NN   (WW*VV)          // 4096
#define PAD  68               // padded stride for d-major GEMM1 tiles

typedef unsigned long long ull;

// ---------------------------------------------------------------------------
// Scratch (static device globals)
// ---------------------------------------------------------------------------
__device__ float g_A   [BB*WW*DD];
__device__ float g_BtT [BB*DD*VV];
__device__ float g_relaT[DD*RR];
__device__ float g_AW  [BB*WW*DD];
__device__ float g_BW  [BB*VV*DD];
__device__ float g_RW  [RR*DD];
__device__ uint32_t g_w1bT [DD*DD/2];            // w1^T bf16-hi pairs [n][kpair]
__device__ uint32_t g_rwbHi[DD*RR/2];            // RW^T bf16-hi pairs [n][kpair(32)]
__device__ uint32_t g_rwbLo[DD*RR/2];            // RW^T bf16-lo pairs
__device__ __nv_bfloat16 g_tvh[(size_t)BB*NN*DD]; // tuple_vec bf16 (32 MB)
__device__ float g_att [BB*NN];
__device__ float g_fuse[BB*DD];

// ---------------------------------------------------------------------------
// helpers
// ---------------------------------------------------------------------------
__device__ __forceinline__ float tanh_fast(float x) {
    float y; asm("tanh.approx.f32 %0, %1;" : "=f"(y) : "f"(x)); return y;
}
__device__ __forceinline__ ull fma2(ull a, ull b, ull c) {
    ull d; asm("fma.rn.f32x2 %0, %1, %2, %3;" : "=l"(d) : "l"(a), "l"(b), "l"(c)); return d;
}
__device__ __forceinline__ ull pack2(float x) {
    ull r; asm("mov.b64 %0, {%1, %1};" : "=l"(r) : "f"(x)); return r;
}
__device__ __forceinline__ float2 unpack2(ull v) {
    float2 f; asm("mov.b64 {%0, %1}, %2;" : "=f"(f.x), "=f"(f.y) : "l"(v)); return f;
}
__device__ __forceinline__ uint32_t smem_u32(const void* p) {
    uint32_t a;
    asm("{ .reg .u64 tmp; cvta.to.shared.u64 tmp, %1; cvt.u32.u64 %0, tmp; }"
        : "=r"(a) : "l"(p));
    return a;
}
__device__ __forceinline__ void cp_async16(uint32_t daddr, const void* src) {
    asm volatile("cp.async.cg.shared.global [%0], [%1], 16;"
                 :: "r"(daddr), "l"(src) : "memory");
}
#define CP_COMMIT() asm volatile("cp.async.commit_group;" ::: "memory")
#define CP_WAIT0()  asm volatile("cp.async.wait_group 0;" ::: "memory")

// m16n8k16 bf16 MMA (HMMA path; sm_80+, not an 'a' feature)
__device__ __forceinline__ void mma_bf16(float c[4],
    uint32_t a0, uint32_t a1, uint32_t a2, uint32_t a3,
    uint32_t b0, uint32_t b1)
{
    asm volatile(
        "mma.sync.aligned.m16n8k16.row.col.f32.bf16.bf16.f32 "
        "{%0,%1,%2,%3}, {%4,%5,%6,%7}, {%8,%9}, {%0,%1,%2,%3};"
        : "+f"(c[0]), "+f"(c[1]), "+f"(c[2]), "+f"(c[3])
        : "r"(a0), "r"(a1), "r"(a2), "r"(a3), "r"(b0), "r"(b1));
}

// pack two floats into bf16x2 u32 (low = first elem)
__device__ __forceinline__ uint32_t pkbf2(float a, float b) {
    return (uint32_t)__bfloat16_as_ushort(__float2bfloat16_rn(a))
         | ((uint32_t)__bfloat16_as_ushort(__float2bfloat16_rn(b)) << 16);
}
__device__ __forceinline__ float bf16hi_f(float x) {
    return __bfloat162float(__float2bfloat16_rn(x));
}

// ---------------------------------------------------------------------------
// Kernel W: g_w1bT[n][p] = bf16 pair (w1[2p][n], w1[2p+1][n]). 128 x 256.
// ---------------------------------------------------------------------------
__global__ __launch_bounds__(256) void kW1T(const float* __restrict__ aw1)
{
    const int p = blockIdx.x;
    const int n = threadIdx.x;
    const float a = aw1[(2 * p) * DD + n];
    const float b = aw1[(2 * p + 1) * DD + n];
    g_w1bT[n * 128 + p] = pkbf2(a, b);
}

// ---------------------------------------------------------------------------
// Kernel RT: RW^T hi/lo bf16 pair images. Runs AFTER kPre. 32 x 256.
// ---------------------------------------------------------------------------
__global__ __launch_bounds__(256) void kRWT()
{
    const int p = blockIdx.x;     // 0..31 (k pairs over R=64)
    const int n = threadIdx.x;    // 0..255 (output col)
    const float a = g_RW[(2 * p) * DD + n];
    const float b = g_RW[(2 * p + 1) * DD + n];
    g_rwbHi[n * 32 + p] = pkbf2(a, b);
    g_rwbLo[n * 32 + p] = pkbf2(a - bf16hi_f(a), b - bf16hi_f(b));
}

// ---------------------------------------------------------------------------
// Kernel P: gather + AW/BW/RW precompute + transposed copies (132 blocks)
// ---------------------------------------------------------------------------
__global__ __launch_bounds__(256) void kPre(
    const int* __restrict__ head, const int* __restrict__ tail,
    const float* __restrict__ emb, const float* __restrict__ rela,
    const float* __restrict__ fc_w, const float* __restrict__ fc_b)
{
    __shared__ float sX[16][257];
    const int g = blockIdx.x, t = threadIdx.x;
    const int kind = (g < 64) ? 0 : (g < 128 ? 1 : 2);
    const int row0 = ((kind == 0) ? g : (kind == 1) ? (g - 64) : (g - 128)) * 16;

    #pragma unroll 4
    for (int rr = 0; rr < 16; ++rr) {
        const int row = row0 + rr;
        float v;
        if (kind == 0)      v = emb[(size_t)head[row] * DD + t];
        else if (kind == 1) v = emb[(size_t)tail[row] * DD + t];
        else                v = rela[row * DD + t];
        sX[rr][t] = v;
        if (kind == 0)      g_A[row * DD + t] = v;
    }
    __syncthreads();

    const float* Wp = fc_w + (size_t)kind * DD * DD;
    float acc[16];
    #pragma unroll
    for (int r = 0; r < 16; ++r) acc[r] = (kind == 0) ? fc_b[t] : 0.0f;

    #pragma unroll 4
    for (int k = 0; k < DD; ++k) {
        const float wv = Wp[k * DD + t];
        #pragma unroll
        for (int r = 0; r < 16; ++r) acc[r] = fmaf(sX[r][k], wv, acc[r]);
    }

    float* dst = (kind == 0) ? g_AW : (kind == 1) ? g_BW : g_RW;
    #pragma unroll
    for (int r = 0; r < 16; ++r) dst[(row0 + r) * DD + t] = acc[r];

    if (kind != 0) {
        float* dstT = (kind == 1)
            ? (g_BtT + (size_t)(row0 >> 6) * DD * VV + (row0 & 63))
            : (g_relaT + row0);
        #pragma unroll
        for (int it = 0; it < 4; ++it) {
            const int f = it * 256 + t;
            const int d = f >> 2;
            const int q = f & 3;
            float4 v;
            v.x = sX[q * 4 + 0][d];
            v.y = sX[q * 4 + 1][d];
            v.z = sX[q * 4 + 2][d];
            v.w = sX[q * 4 + 3][d];
            *(float4*)&dstT[d * 64 + q * 4] = v;
        }
    }
}

// ---------------------------------------------------------------------------
// Kernel M: fused per (b,i). 1024 blocks x 256 threads.
//   GEMM1 scalar fp32 (mask-precision-critical), softmax,
//   GEMM2 tensor bf16-split 3-pass, GEMM3 tensor bf16-split 2-pass, epilogue.
// smem (float offsets):
//   [0, 17408)    : GEMM1 s1h/s2h [128][68] -> later RWBhi/RWBlo u32 [256][36]
//   [18432, 22784): sP [64][68]
//   [22784, 27392): sPAhi/sPAlo u32 [64][36]
//   [27392, 44288): sAhi/sAlo u32 [64][132]
//   [44288, 54528): w1 bufs 2 x u32[256][20]
//   [54528, 55616): sA, sAW, sb1, sw2 (256 each), sred (64)
// ---------------------------------------------------------------------------
#define SM_S1    0
#define SM_S2    8704
#define SM_RWH   0
#define SM_RWL   9216
#define SM_SP    18432
#define SM_PAH   22784
#define SM_PAL   25088
#define SM_AH    27392
#define SM_AL    35840
#define SM_WB    44288
#define SM_SA    54528
#define SM_SAW   54784
#define SM_SB1   55040
#define SM_SW2   55296
#define SM_SRED  55552
#define SMEM_M_FLOATS 55616
#define SMEM_M_BYTES  (SMEM_M_FLOATS * 4)

// load one 32-k w1 chunk (16 pairs/row, stride 20 u32) via cp.async
__device__ __forceinline__ void load_w1_chunk32(uint32_t dst_base, int kk, int t)
{
    const uint32_t* src = g_w1bT + kk * 16;
    #pragma unroll
    for (int it = 0; it < 4; ++it) {
        const int idx = it * 256 + t;      // 1024 uint4s
        const int n  = idx >> 2;
        const int q4 = (idx & 3) * 4;
        cp_async16(dst_base + (uint32_t)(n * 80 + q4 * 4), src + n * 128 + q4);
    }
}

__global__ __launch_bounds__(256, 1) void kMain(
    const float* __restrict__ att_b1, const float* __restrict__ att_w2,
    const float* __restrict__ att_b2, float* __restrict__ out_ns)
{
    const int t  = threadIdx.x;
    const int b  = blockIdx.x >> 6;
    const int i  = blockIdx.x & 63;
    const int lane = t & 31;
    const int wid  = t >> 5;
    // GEMM1 mapping (4x4 tiles, 16x16 grid)
    const int tx = t & 15, ty = t >> 4;
    const int j0g = ty * 4, r0 = tx * 4;
    // MMA mapping (GEMM2 & GEMM3)
    const int gid = lane >> 2, tid4 = lane & 3;
    const int wm = (wid & 3) * 16;        // warp m-tile base
    const int wn = (wid >> 2) * 128;      // warp n-half base

    extern __shared__ float sm[];
    float*    s1h  = sm + SM_S1;
    float*    s2h  = sm + SM_S2;
    uint32_t* sRWH = (uint32_t*)(sm + SM_RWH);   // [256][36]
    uint32_t* sRWL = (uint32_t*)(sm + SM_RWL);
    float*    sP   = sm + SM_SP;
    uint32_t* sPAH = (uint32_t*)(sm + SM_PAH);   // [64][36]
    uint32_t* sPAL = (uint32_t*)(sm + SM_PAL);
    uint32_t* sAhi = (uint32_t*)(sm + SM_AH);    // [64][132]
    uint32_t* sAlo = (uint32_t*)(sm + SM_AL);
    uint32_t* sWB  = (uint32_t*)(sm + SM_WB);    // 2 x [256][20]
    float*    sA   = sm + SM_SA;
    float*    sAW  = sm + SM_SAW;
    float*    sb1  = sm + SM_SB1;
    float*    sw2  = sm + SM_SW2;
    float*    sred = sm + SM_SRED;

    const int rowA = b * WW + i;
    sA [t] = g_A [rowA * DD + t];
    sAW[t] = g_AW[rowA * DD + t];
    sb1[t] = att_b1[t];
    sw2[t] = att_w2[t];
    __syncthreads();

    // ---- GEMM1: S = H @ rela^T (64x64, K=256 in 2 halves), scalar fp32 ----
    ull c1[4][2];
    #pragma unroll
    for (int u = 0; u < 4; ++u) { c1[u][0] = 0ull; c1[u][1] = 0ull; }

    for (int half = 0; half < 2; ++half) {
        #pragma unroll 2
        for (int it = 0; it < 8; ++it) {
            const int f = it * 256 + t;
            const int d = f >> 4;
            const int c = (f & 15) * 4;
            const int dg = half * 128 + d;
            float4 bv = *(const float4*)&g_BtT[(size_t)b * DD * VV + dg * 64 + c];
            const float sa = sA[dg];
            bv.x *= sa; bv.y *= sa; bv.z *= sa; bv.w *= sa;
            *(float4*)&s1h[d * PAD + c] = bv;
            *(float4*)&s2h[d * PAD + c] = *(const float4*)&g_relaT[dg * 64 + c];
        }
        __syncthreads();

        #pragma unroll 4
        for (int d = 0; d < 128; ++d) {
            const float4 h4 = *(const float4*)&s1h[d * PAD + j0g];
            const ulonglong2 r2 = *(const ulonglong2*)&s2h[d * PAD + r0];
            const ull hp[4] = {pack2(h4.x), pack2(h4.y), pack2(h4.z), pack2(h4.w)};
            #pragma unroll
            for (int u = 0; u < 4; ++u) {
                c1[u][0] = fma2(hp[u], r2.x, c1[u][0]);
                c1[u][1] = fma2(hp[u], r2.y, c1[u][1]);
            }
        }
        __syncthreads();
    }
    #pragma unroll
    for (int u = 0; u < 4; ++u) {
        const float2 lo = unpack2(c1[u][0]);
        const float2 hi = unpack2(c1[u][1]);
        *(float4*)&sP[(j0g + u) * PAD + r0] = make_float4(lo.x, lo.y, hi.x, hi.y);
    }
    __syncthreads();

    // async: RWB hi/lo images + w1 chunk0 (overlaps softmax)
    {
        const uint32_t hB = smem_u32(sRWH);
        const uint32_t lB = smem_u32(sRWL);
        #pragma unroll
        for (int it = 0; it < 8; ++it) {
            const int idx = it * 256 + t;   // 2048 uint4s per image
            const int n  = idx >> 3;
            const int q4 = (idx & 7) * 4;
            cp_async16(hB + (uint32_t)(n * 144 + q4 * 4), g_rwbHi + n * 32 + q4);
            cp_async16(lB + (uint32_t)(n * 144 + q4 * 4), g_rwbLo + n * 32 + q4);
        }
        load_w1_chunk32(smem_u32(sWB), 0, t);
        CP_COMMIT();
    }

    // ---- mask + row softmax over R; also pack P hi/lo pairs for GEMM2 ----
    {
        const int j = t >> 2, q = t & 3;
        const float nul = sP[j * PAD + 63];
        float v[16];
        float mx = -1e30f;
        #pragma unroll
        for (int m = 0; m < 16; ++m) {
            float s = sP[j * PAD + q * 16 + m];
            s = (s <= nul) ? -1e10f : s;
            v[m] = s;
            mx = fmaxf(mx, s);
        }
        mx = fmaxf(mx, __shfl_xor_sync(0xffffffffu, mx, 1));
        mx = fmaxf(mx, __shfl_xor_sync(0xffffffffu, mx, 2));
        float se = 0.0f;
        #pragma unroll
        for (int m = 0; m < 16; ++m) { v[m] = expf(v[m] - mx); se += v[m]; }
        se += __shfl_xor_sync(0xffffffffu, se, 1);
        se += __shfl_xor_sync(0xffffffffu, se, 2);
        const float inv = 1.0f / se;
        #pragma unroll
        for (int m = 0; m < 16; ++m) {
            v[m] *= inv;
            sP[j * PAD + q * 16 + m] = v[m];
        }
        #pragma unroll
        for (int mm = 0; mm < 8; ++mm) {
            const float x0 = v[2 * mm], x1 = v[2 * mm + 1];
            sPAH[j * 36 + q * 8 + mm] = pkbf2(x0, x1);
            sPAL[j * 36 + q * 8 + mm] = pkbf2(x0 - bf16hi_f(x0), x1 - bf16hi_f(x1));
        }
    }
    __syncthreads();

    // write norm_scores
    const size_t ns_base = ((size_t)(b * NN + i * VV)) * RR;
    #pragma unroll
    for (int it = 0; it < 16; ++it) {
        const int l = it * 256 + t;
        const int j = l >> 6, r = l & 63;
        out_ns[ns_base + (size_t)j * RR + r] = sP[j * PAD + r];
    }
    CP_WAIT0();
    __syncthreads();

    // ---- GEMM2: PV = P @ RW via mma bf16-split 3-pass (M=64,N=256,K=64) ----
    float a2[16][4];
    #pragma unroll
    for (int nt = 0; nt < 16; ++nt)
        #pragma unroll
        for (int e = 0; e < 4; ++e) a2[nt][e] = 0.0f;

    const int pr0 = (wm + gid) * 36;
    const int pr1 = (wm + gid + 8) * 36;

    #pragma unroll
    for (int ks = 0; ks < 4; ++ks) {
        const int gp = ks * 8 + tid4;
        const uint32_t h0 = sPAH[pr0 + gp],     l0 = sPAL[pr0 + gp];
        const uint32_t h1 = sPAH[pr1 + gp],     l1 = sPAL[pr1 + gp];
        const uint32_t h2 = sPAH[pr0 + gp + 4], l2 = sPAL[pr0 + gp + 4];
        const uint32_t h3 = sPAH[pr1 + gp + 4], l3 = sPAL[pr1 + gp + 4];
        #pragma unroll
        for (int nt = 0; nt < 16; ++nt) {
            const int n = wn + nt * 8 + gid;
            const uint32_t bh0 = sRWH[n * 36 + gp];
            const uint32_t bh1 = sRWH[n * 36 + gp + 4];
            const uint32_t bl0 = sRWL[n * 36 + gp];
            const uint32_t bl1 = sRWL[n * 36 + gp + 4];
            mma_bf16(a2[nt], h0, h1, h2, h3, bh0, bh1);
            mma_bf16(a2[nt], l0, l1, l2, l3, bh0, bh1);
            mma_bf16(a2[nt], h0, h1, h2, h3, bl0, bl1);
        }
    }

    // tv epilogue: tanh(AW + BW + PV) -> g_tvh + sAhi/sAlo (GEMM3 A frags)
    {
        const int row0 = wm + gid, row1 = wm + gid + 8;
        const size_t tvb0 = ((size_t)(b * NN + i * VV + row0)) * DD;
        const size_t tvb1 = ((size_t)(b * NN + i * VV + row1)) * DD;
        const float* bwr0 = g_BW + (size_t)(b * VV + row0) * DD;
        const float* bwr1 = g_BW + (size_t)(b * VV + row1) * DD;
        uint32_t* tvu = (uint32_t*)g_tvh;
        #pragma unroll
        for (int nt = 0; nt < 16; ++nt) {
            const int c = wn + nt * 8 + 2 * tid4;
            const float aw0 = sAW[c], aw1v = sAW[c + 1];
            const float2 bw0 = *(const float2*)(bwr0 + c);
            const float2 bw1 = *(const float2*)(bwr1 + c);
            const float t00 = tanh_fast(a2[nt][0] + aw0  + bw0.x);
            const float t01 = tanh_fast(a2[nt][1] + aw1v + bw0.y);
            const float t10 = tanh_fast(a2[nt][2] + aw0  + bw1.x);
            const float t11 = tanh_fast(a2[nt][3] + aw1v + bw1.y);
            tvu[(tvb0 + c) >> 1] = pkbf2(t00, t01);
            tvu[(tvb1 + c) >> 1] = pkbf2(t10, t11);
            const int p = (c >> 1);
            sAhi[row0 * 132 + p] = pkbf2(t00, t01);
            sAlo[row0 * 132 + p] = pkbf2(t00 - bf16hi_f(t00), t01 - bf16hi_f(t01));
            sAhi[row1 * 132 + p] = pkbf2(t10, t11);
            sAlo[row1 * 132 + p] = pkbf2(t10 - bf16hi_f(t10), t11 - bf16hi_f(t11));
        }
    }
    __syncthreads();

    // ---- GEMM3: Hid = tv @ w1 via mma bf16 split-A 2-pass, 8 chunks of 32k ----
    float a3[16][4];
    #pragma unroll
    for (int nt = 0; nt < 16; ++nt)
        #pragma unroll
        for (int e = 0; e < 4; ++e) a3[nt][e] = 0.0f;

    const int ar0 = (wm + gid) * 132;
    const int ar1 = (wm + gid + 8) * 132;

    for (int kk = 0; kk < 8; ++kk) {
        if (kk < 7) {
            load_w1_chunk32(smem_u32(sWB + ((kk + 1) & 1) * 5120), kk + 1, t);
            CP_COMMIT();
        }
        const uint32_t* wb = sWB + (kk & 1) * 5120;

        #pragma unroll
        for (int ks = 0; ks < 2; ++ks) {
            const int gp = kk * 16 + ks * 8 + tid4;
            const uint32_t h0 = sAhi[ar0 + gp],     l0 = sAlo[ar0 + gp];
            const uint32_t h1 = sAhi[ar1 + gp],     l1 = sAlo[ar1 + gp];
            const uint32_t h2 = sAhi[ar0 + gp + 4], l2 = sAlo[ar0 + gp + 4];
            const uint32_t h3 = sAhi[ar1 + gp + 4], l3 = sAlo[ar1 + gp + 4];
            const int bq = ks * 8 + tid4;
            #pragma unroll
            for (int nt = 0; nt < 16; ++nt) {
                const int n = wn + nt * 8 + gid;
                const uint32_t b0 = wb[n * 20 + bq];
                const uint32_t b1 = wb[n * 20 + bq + 4];
                mma_bf16(a3[nt], h0, h1, h2, h3, b0, b1);
                mma_bf16(a3[nt], l0, l1, l2, l3, b0, b1);
            }
        }
        if (kk < 7) { CP_WAIT0(); __syncthreads(); }
    }

    // ---- epilogue: att[row] = sum_col tanh(hid + b1) * w2 + b2 ----
    float p0 = 0.0f, p1 = 0.0f;
    #pragma unroll
    for (int nt = 0; nt < 16; ++nt) {
        const int col = wn + nt * 8 + 2 * tid4;
        p0 = fmaf(tanh_fast(a3[nt][0] + sb1[col]),     sw2[col],     p0);
        p0 = fmaf(tanh_fast(a3[nt][1] + sb1[col + 1]), sw2[col + 1], p0);
        p1 = fmaf(tanh_fast(a3[nt][2] + sb1[col]),     sw2[col],     p1);
        p1 = fmaf(tanh_fast(a3[nt][3] + sb1[col + 1]), sw2[col + 1], p1);
    }
    p0 += __shfl_xor_sync(0xffffffffu, p0, 1);
    p0 += __shfl_xor_sync(0xffffffffu, p0, 2);
    p1 += __shfl_xor_sync(0xffffffffu, p1, 1);
    p1 += __shfl_xor_sync(0xffffffffu, p1, 2);

    if (wid < 4) {
        if (tid4 == 0) { sred[wm + gid] = p0; sred[wm + gid + 8] = p1; }
    }
    __syncthreads();
    if (wid >= 4) {
        if (tid4 == 0) { sred[wm + gid] += p0; sred[wm + gid + 8] += p1; }
    }
    __syncthreads();
    if (t < 64)
        g_att[b * NN + i * VV + t] = sred[t] + att_b2[0];
}

// ---------------------------------------------------------------------------
// Kernel F1: softmax over N of att per batch; writes att_norms; zeroes g_fuse
// ---------------------------------------------------------------------------
__global__ __launch_bounds__(256) void kAtt(float* __restrict__ out_attn)
{
    const int b = blockIdx.x, t = threadIdx.x;
    __shared__ float red[8];
    float vals[16];
    float mx = -1e30f;
    #pragma unroll
    for (int it = 0; it < 16; ++it) {
        vals[it] = g_att[b * NN + it * 256 + t];
        mx = fmaxf(mx, vals[it]);
    }
    #pragma unroll
    for (int o = 16; o; o >>= 1) mx = fmaxf(mx, __shfl_xor_sync(0xffffffffu, mx, o));
    if ((t & 31) == 0) red[t >> 5] = mx;
    __syncthreads();
    float bm = red[0];
    #pragma unroll
    for (int w = 1; w < 8; ++w) bm = fmaxf(bm, red[w]);
    __syncthreads();

    float s = 0.0f;
    #pragma unroll
    for (int it = 0; it < 16; ++it) { vals[it] = expf(vals[it] - bm); s += vals[it]; }
    #pragma unroll
    for (int o = 16; o; o >>= 1) s += __shfl_xor_sync(0xffffffffu, s, o);
    if ((t & 31) == 0) red[t >> 5] = s;
    __syncthreads();
    float bs = 0.0f;
    #pragma unroll
    for (int w = 0; w < 8; ++w) bs += red[w];
    const float inv = 1.0f / bs;
    #pragma unroll
    for (int it = 0; it < 16; ++it)
        out_attn[b * NN + it * 256 + t] = vals[it] * inv;
    g_fuse[b * DD + t] = 0.0f;
}

// ---------------------------------------------------------------------------
// Kernel F2: fuse = sum_n att_norms[n] * tv[n,:]  (1024 blocks, bf16 tv)
// ---------------------------------------------------------------------------
__global__ __launch_bounds__(256) void kFuse(const float* __restrict__ attn)
{
    const int b = blockIdx.x >> 6, ch = blockIdx.x & 63, t = threadIdx.x;
    __shared__ float sa[64];
    const int n0 = ch * 64;
    if (t < 64) sa[t] = attn[b * NN + n0 + t];
    __syncthreads();

    const __nv_bfloat16* tvp = g_tvh + ((size_t)(b * NN + n0)) * DD + t;
    float a0 = 0, a1 = 0, a2 = 0, a3 = 0, a4 = 0, a5 = 0, a6 = 0, a7 = 0;
    #pragma unroll
    for (int n = 0; n < 64; n += 8) {
        a0 = fmaf(sa[n + 0], __bfloat162float(tvp[(size_t)(n + 0) * DD]), a0);
        a1 = fmaf(sa[n + 1], __bfloat162float(tvp[(size_t)(n + 1) * DD]), a1);
        a2 = fmaf(sa[n + 2], __bfloat162float(tvp[(size_t)(n + 2) * DD]), a2);
        a3 = fmaf(sa[n + 3], __bfloat162float(tvp[(size_t)(n + 3) * DD]), a3);
        a4 = fmaf(sa[n + 4], __bfloat162float(tvp[(size_t)(n + 4) * DD]), a4);
        a5 = fmaf(sa[n + 5], __bfloat162float(tvp[(size_t)(n + 5) * DD]), a5);
        a6 = fmaf(sa[n + 6], __bfloat162float(tvp[(size_t)(n + 6) * DD]), a6);
        a7 = fmaf(sa[n + 7], __bfloat162float(tvp[(size_t)(n + 7) * DD]), a7);
    }
    atomicAdd(&g_fuse[b * DD + t], ((a0 + a1) + (a2 + a3)) + ((a4 + a5) + (a6 + a7)));
}

// ---------------------------------------------------------------------------
// Kernel F3: logits[b] = fuse . out_w + out_b
// ---------------------------------------------------------------------------
__global__ __launch_bounds__(256) void kLogits(
    float* __restrict__ out, const float* __restrict__ ow, const float* __restrict__ ob)
{
    const int b = blockIdx.x, t = threadIdx.x;
    __shared__ float red[8];
    float v = g_fuse[b * DD + t] * ow[t];
    #pragma unroll
    for (int o = 16; o; o >>= 1) v += __shfl_xor_sync(0xffffffffu, v, o);
    if ((t & 31) == 0) red[t >> 5] = v;
    __syncthreads();
    if (t == 0) {
        float s = 0.0f;
        #pragma unroll
        for (int w = 0; w < 8; ++w) s += red[w];
        out[b] = s + ob[0];
    }
}

// ---------------------------------------------------------------------------
// Launch
// ---------------------------------------------------------------------------
extern "C" void kernel_launch(void* const* d_in, const int* in_sizes, int n_in,
                              void* d_out, int out_size)
{
    const int*   head = (const int*)d_in[0];
    const int*   tail = (const int*)d_in[1];
    const float* emb  = (const float*)d_in[2];
    const float* rela = (const float*)d_in[3];
    const float* fc_w = (const float*)d_in[4];
    const float* fc_b = (const float*)d_in[5];
    const float* aw1  = (const float*)d_in[6];
    const float* ab1  = (const float*)d_in[7];
    const float* aw2  = (const float*)d_in[8];
    const float* ab2  = (const float*)d_in[9];
    const float* ow   = (const float*)d_in[10];
    const float* ob   = (const float*)d_in[11];

    float* out        = (float*)d_out;
    float* out_logits = out;
    float* out_attn   = out + BB;
    float* out_ns     = out + BB + BB * NN;

    cudaFuncSetAttribute(kMain, cudaFuncAttributeMaxDynamicSharedMemorySize, SMEM_M_BYTES);

    kPre   <<<132,   256>>>(head, tail, emb, rela, fc_w, fc_b);
    kW1T   <<<128,   256>>>(aw1);
    kRWT   <<<32,    256>>>();
    kMain  <<<BB*WW, 256, SMEM_M_BYTES>>>(ab1, aw2, ab2, out_ns);
    kAtt   <<<BB,    256>>>(out_attn);
    kFuse  <<<BB*64, 256>>>(out_attn);
    kLogits<<<BB,    256>>>(out_logits, ow, ob);
}